// round 5
// baseline (speedup 1.0000x reference)
#include <cuda_runtime.h>
#include <math.h>

#define S_ 256
#define B_ 512
#define H_ 256
#define H3 768
#define VOCAB_ 32000
#define NSTACK 2
#define SSIZE 64
#define ELEM 64
#define NBLK 256

// ---------------- device scratch (static, no allocation) ----------------
__device__ float g_EMB_GI[VOCAB_ * H3];       // emb @ W_ih^T + b_ih
__device__ float g_WihT[H_ * H3];             // [k][n]
__device__ float g_WhhT[H_ * H3];             // [k][n]
__device__ float g_WstkT[H_ * (NSTACK * ELEM)];
__device__ float g_Wa1T[H_ * H_];
__device__ float g_h[2][B_ * H_];             // hidden ping-pong
__device__ float g_PV[2][B_ * NSTACK * ELEM]; // push_vals ping-pong
__device__ float g_P[2][B_ * NSTACK * 3];     // act probs ping-pong
__device__ float g_spart[2][S_ * B_];         // attention score partials
__device__ unsigned int g_bar;                // grid barrier counter

__device__ __forceinline__ float sigmoidf_(float x) { return 1.f / (1.f + expf(-x)); }

// ---------------- packed f32x2 helpers ----------------
__device__ __forceinline__ unsigned long long pack2(float x) {
    unsigned long long d;
    unsigned int u = __float_as_uint(x);
    asm("mov.b64 %0, {%1, %1};" : "=l"(d) : "r"(u));
    return d;
}
__device__ __forceinline__ void fma2(unsigned long long& d, unsigned long long a,
                                     unsigned long long b) {
    asm("fma.rn.f32x2 %0, %1, %2, %0;" : "+l"(d) : "l"(a), "l"(b));
}
__device__ __forceinline__ float2 unpack2(unsigned long long v) {
    unsigned int lo, hi;
    asm("mov.b64 {%0, %1}, %2;" : "=r"(lo), "=r"(hi) : "l"(v));
    return make_float2(__uint_as_float(lo), __uint_as_float(hi));
}

// ---------------- prep kernels (split so persist = launch #5 for ncu) ----------------
__global__ void prep_a(const float* __restrict__ W_ih) {
    int idx = blockIdx.x * 256 + threadIdx.x;
    if (idx < H3 * H_) { int r = idx % H3, c = idx / H3; g_WihT[idx] = W_ih[r * H_ + c]; }
}
__global__ void prep_b(const float* __restrict__ W_hh) {
    int idx = blockIdx.x * 256 + threadIdx.x;
    if (idx < H3 * H_) { int r = idx % H3, c = idx / H3; g_WhhT[idx] = W_hh[r * H_ + c]; }
}
__global__ void prep_c(const float* __restrict__ W_stk, const float* __restrict__ Wa1) {
    int idx = blockIdx.x * 256 + threadIdx.x;
    if (idx < (NSTACK * ELEM) * H_) {
        int r = idx % (NSTACK * ELEM), c = idx / (NSTACK * ELEM);
        g_WstkT[idx] = W_stk[r * H_ + c];
    }
    if (idx < H_ * H_) { int r = idx % H_, c = idx / H_; g_Wa1T[idx] = Wa1[r * H_ + c]; }
}
__global__ void prep_d() {
    int idx = blockIdx.x * 256 + threadIdx.x;
    if (idx < B_ * H_) g_h[0][idx] = 0.f;
    if (idx == 0) g_bar = 0u;
}

// ---------------- 128x128x16 SGEMM with f32x2 ----------------
template <bool SCORE>
__global__ void __launch_bounds__(256) sgemm128_k(
    const float* __restrict__ A, const float* __restrict__ Bm,
    const float* __restrict__ bias, float* __restrict__ C,
    const float* __restrict__ Wa2,
    int M, int N, int K)
{
    __shared__ __align__(16) float As[16][128];   // [k][m]
    __shared__ __align__(16) float Bs[16][128];   // [k][n]
    int tid = threadIdx.x;
    int m0 = blockIdx.y * 128, n0 = blockIdx.x * 128;
    int tx = tid & 15, ty = tid >> 4;

    unsigned long long acc[2][2][4][2];
#pragma unroll
    for (int a = 0; a < 2; a++)
#pragma unroll
        for (int b = 0; b < 2; b++)
#pragma unroll
            for (int c = 0; c < 4; c++) { acc[a][b][c][0] = 0ull; acc[a][b][c][1] = 0ull; }

    for (int k0 = 0; k0 < K; k0 += 16) {
#pragma unroll
        for (int i = 0; i < 2; i++) {
            int f = tid * 2 + i;
            int arow = f >> 2, aq = (f & 3) * 4;
            float4 v = *(const float4*)&A[(size_t)(m0 + arow) * K + k0 + aq];
            As[aq + 0][arow] = v.x; As[aq + 1][arow] = v.y;
            As[aq + 2][arow] = v.z; As[aq + 3][arow] = v.w;
            int brow = f >> 5, bc = (f & 31) * 4;
            *(float4*)&Bs[brow][bc] = *(const float4*)&Bm[(size_t)(k0 + brow) * N + n0 + bc];
        }
        __syncthreads();
#pragma unroll
        for (int kk = 0; kk < 16; kk++) {
            float4 a0 = *(float4*)&As[kk][ty * 4];
            float4 a1 = *(float4*)&As[kk][ty * 4 + 64];
            unsigned long long ap[2][4];
            ap[0][0] = pack2(a0.x); ap[0][1] = pack2(a0.y);
            ap[0][2] = pack2(a0.z); ap[0][3] = pack2(a0.w);
            ap[1][0] = pack2(a1.x); ap[1][1] = pack2(a1.y);
            ap[1][2] = pack2(a1.z); ap[1][3] = pack2(a1.w);
            ulonglong2 b0 = *(ulonglong2*)&Bs[kk][tx * 4];
            ulonglong2 b1 = *(ulonglong2*)&Bs[kk][tx * 4 + 64];
#pragma unroll
            for (int ic = 0; ic < 2; ic++)
#pragma unroll
                for (int i = 0; i < 4; i++) {
                    fma2(acc[ic][0][i][0], ap[ic][i], b0.x);
                    fma2(acc[ic][0][i][1], ap[ic][i], b0.y);
                    fma2(acc[ic][1][i][0], ap[ic][i], b1.x);
                    fma2(acc[ic][1][i][1], ap[ic][i], b1.y);
                }
        }
        __syncthreads();
    }

    if (!SCORE) {
#pragma unroll
        for (int ic = 0; ic < 2; ic++)
#pragma unroll
            for (int i = 0; i < 4; i++) {
                int m = m0 + ic * 64 + ty * 4 + i;
#pragma unroll
                for (int jc = 0; jc < 2; jc++) {
                    int n = n0 + jc * 64 + tx * 4;
                    float2 p0 = unpack2(acc[ic][jc][i][0]);
                    float2 p1 = unpack2(acc[ic][jc][i][1]);
                    float4 o;
                    o.x = p0.x + bias[n + 0];
                    o.y = p0.y + bias[n + 1];
                    o.z = p1.x + bias[n + 2];
                    o.w = p1.y + bias[n + 3];
                    *(float4*)&C[(size_t)m * N + n] = o;
                }
            }
    } else {
        float4 bb[2], ww[2];
#pragma unroll
        for (int jc = 0; jc < 2; jc++) {
            int n = n0 + jc * 64 + tx * 4;
            bb[jc] = *(const float4*)&bias[n];
            ww[jc] = *(const float4*)&Wa2[n];
        }
#pragma unroll
        for (int ic = 0; ic < 2; ic++)
#pragma unroll
            for (int i = 0; i < 4; i++) {
                float p = 0.f;
#pragma unroll
                for (int jc = 0; jc < 2; jc++) {
                    float2 p0 = unpack2(acc[ic][jc][i][0]);
                    float2 p1 = unpack2(acc[ic][jc][i][1]);
                    p += tanhf(p0.x + bb[jc].x) * ww[jc].x;
                    p += tanhf(p0.y + bb[jc].y) * ww[jc].y;
                    p += tanhf(p1.x + bb[jc].z) * ww[jc].z;
                    p += tanhf(p1.y + bb[jc].w) * ww[jc].w;
                }
#pragma unroll
                for (int off = 8; off > 0; off >>= 1)
                    p += __shfl_xor_sync(0xffffffffu, p, off);
                if (tx == 0) {
                    int m = m0 + ic * 64 + ty * 4 + i;
                    g_spart[blockIdx.x][m] = p;
                }
            }
    }
}

// ---------------- persistent recurrence kernel ----------------
// 256 blocks x 256 threads, all co-resident (2/SM). Grid barrier per step.
// blocks [0,128):   GRU tile: 16 batches x 64 h-cols x 3 gates
// blocks [128,256): AUX tile: 8 batches x 64 pv-cols; jt==0 also ACT (probs)
// every block owns 4 stacks in SMEM for the whole recurrence.
// SMEM: stacks 65536B | GRU: As 32*18*4=2304B, Bs 3*32*68*4=26112B (AUX aliases)
#define SMEM_DYN (65536 + 2304 + 26112)

__global__ void __launch_bounds__(256, 2) persist_k(
    const int* __restrict__ tokens,
    const float* __restrict__ b_ih,
    const float* __restrict__ b_hh,
    const float* __restrict__ W_act,
    const float* __restrict__ b_act,
    const float* __restrict__ b_stk,
    const float* __restrict__ empty_elem,
    float* __restrict__ outputs,
    float* __restrict__ stacks_out)
{
    extern __shared__ __align__(16) float smem[];
    float* stk = smem;                 // 4 * 4096
    float* gA  = smem + 16384;         // [k(32)][m(16)+pad2]
    float* gB  = gA + 32 * 18;         // [3][32][64+pad4]
    float* aA  = gA;                   // [k(32)][m(8)+pad2]
    float* aB  = aA + 320;             // [32][64+pad4]
    float* lg  = aB + 32 * 68;         // 48 logits

    int tid = threadIdx.x;
    int blk = blockIdx.x;
    int e   = tid & 63;
    int qr  = (tid >> 6) * 16;
    int tx  = tid & 31, ty = tid >> 5;
    float emp = empty_elem[e];

    // init this block's 4 stacks to empty
    for (int i = tid; i < 4 * 4096; i += 256) stk[i] = empty_elem[i & 63];

    const bool isGRU = blk < 128;
    int mt = blk >> 2, jt = blk & 3;          // GRU mapping
    int ai = blk - 128, amt = ai >> 1, ajt = ai & 1;  // AUX mapping

    for (int s = 0; s < S_; s++) {
        // ---- stack update for step s-1 (SMEM-resident) ----
        if (s > 0) {
            int ph = (s - 1) & 1;
#pragma unroll
            for (int st = 0; st < 4; st++) {
                int sid = blk * 4 + st;
                int b = sid >> 1, n = sid & 1;
                float pp  = __ldcg(&g_P[ph][sid * 3 + 0]);
                float po  = __ldcg(&g_P[ph][sid * 3 + 1]);
                float pn  = __ldcg(&g_P[ph][sid * 3 + 2]);
                float pvv = __ldcg(&g_PV[ph][b * (NSTACK * ELEM) + n * ELEM + e]);
                float* Sm = stk + st * 4096;
                float r[18];
#pragma unroll
                for (int i = 0; i < 18; i++) {
                    int row = qr - 1 + i;
                    r[i] = (row >= 0 && row < SSIZE) ? Sm[row * 64 + e] : 0.f;
                }
                __syncthreads();
#pragma unroll
                for (int i = 0; i < 16; i++) {
                    int row = qr + i;
                    float v;
                    if (row == 0)              v = pp * pvv;
                    else if (row == SSIZE - 1) v = emp;
                    else v = fmaf(pp, r[i], fmaf(po, r[i + 2], pn * r[i + 1]));
                    Sm[row * 64 + e] = v;
                }
                __syncthreads();
            }
        }

        const float* hin = g_h[s & 1];
        if (isGRU) {
            float* hout = g_h[(s + 1) & 1];
            int b0 = mt * 16, j0 = jt * 64;
            unsigned long long acc[3][2] = {{0ull,0ull},{0ull,0ull},{0ull,0ull}};
            for (int k0 = 0; k0 < H_; k0 += 32) {
                {   int m = tid >> 4, k2 = (tid & 15) * 2;
                    float2 v = __ldcg((const float2*)&hin[(b0 + m) * H_ + k0 + k2]);
                    gA[k2 * 18 + m] = v.x; gA[(k2 + 1) * 18 + m] = v.y; }
                {   int rI = tid >> 3, c = (tid & 7) * 8;
                    const float* src = &g_WhhT[(size_t)(k0 + rI) * H3 + j0 + c];
#pragma unroll
                    for (int g = 0; g < 3; g++) {
                        *(float4*)&gB[(g * 32 + rI) * 68 + c]     = *(const float4*)(src + g * H_);
                        *(float4*)&gB[(g * 32 + rI) * 68 + c + 4] = *(const float4*)(src + g * H_ + 4);
                    }
                }
                __syncthreads();
#pragma unroll
                for (int kk = 0; kk < 32; kk++) {
                    float2 av = *(float2*)&gA[kk * 18 + ty * 2];
                    unsigned long long a0 = pack2(av.x), a1 = pack2(av.y);
#pragma unroll
                    for (int g = 0; g < 3; g++) {
                        unsigned long long bv = *(unsigned long long*)&gB[(g * 32 + kk) * 68 + tx * 2];
                        fma2(acc[g][0], a0, bv);
                        fma2(acc[g][1], a1, bv);
                    }
                }
                __syncthreads();
            }
            int j = j0 + tx * 2;
            float2 br = *(const float2*)&b_hh[j];
            float2 bz = *(const float2*)&b_hh[H_ + j];
            float2 bn = *(const float2*)&b_hh[2 * H_ + j];
#pragma unroll
            for (int mi = 0; mi < 2; mi++) {
                int b = b0 + ty * 2 + mi;
                int tok = tokens[s * B_ + b];
                const float* gi = (tok == 0) ? b_ih : (g_EMB_GI + (size_t)tok * H3);
                float2 gr = *(const float2*)&gi[j];
                float2 gz = *(const float2*)&gi[H_ + j];
                float2 gn = *(const float2*)&gi[2 * H_ + j];
                float2 hp = __ldcg((const float2*)&hin[b * H_ + j]);
                float2 R = unpack2(acc[0][mi]);
                float2 Z = unpack2(acc[1][mi]);
                float2 N = unpack2(acc[2][mi]);
                float2 o;
                {   float rr = sigmoidf_(gr.x + R.x + br.x);
                    float zz = sigmoidf_(gz.x + Z.x + bz.x);
                    float nn = tanhf(gn.x + rr * (N.x + bn.x));
                    o.x = (1.f - zz) * nn + zz * hp.x; }
                {   float rr = sigmoidf_(gr.y + R.y + br.y);
                    float zz = sigmoidf_(gz.y + Z.y + bz.y);
                    float nn = tanhf(gn.y + rr * (N.y + bn.y));
                    o.y = (1.f - zz) * nn + zz * hp.y; }
                *(float2*)&hout[b * H_ + j] = o;
                *(float2*)&outputs[((size_t)s * B_ + b) * H_ + j] = o;
            }
        } else {
            int b0 = amt * 8, c0 = ajt * 64;
            unsigned long long acc = 0ull;
            float asum = 0.f;
            bool act = (ajt == 0) && (tid < 48);
            int abl = tid / 6, ao = tid % 6;
            for (int k0 = 0; k0 < H_; k0 += 32) {
                {   int m = tid >> 5, kk = tid & 31;
                    aA[kk * 10 + m] = __ldcg(&hin[(b0 + m) * H_ + k0 + kk]); }
                {   int rI = tid >> 3, c = (tid & 7) * 8;
                    const float* src = &g_WstkT[(size_t)(k0 + rI) * (NSTACK * ELEM) + c0 + c];
                    *(float4*)&aB[rI * 68 + c]     = *(const float4*)(src);
                    *(float4*)&aB[rI * 68 + c + 4] = *(const float4*)(src + 4);
                }
                __syncthreads();
#pragma unroll
                for (int kk = 0; kk < 32; kk++) {
                    unsigned long long ap = pack2(aA[kk * 10 + ty]);
                    unsigned long long bv = *(unsigned long long*)&aB[kk * 68 + tx * 2];
                    fma2(acc, ap, bv);
                }
                if (act) {
#pragma unroll 8
                    for (int kk = 0; kk < 32; kk++)
                        asum = fmaf(aA[kk * 10 + abl], W_act[ao * H_ + k0 + kk], asum);
                }
                __syncthreads();
            }
            {   int b = b0 + ty;
                int c = c0 + tx * 2;
                float2 p = unpack2(acc);
                float2 o;
                o.x = tanhf(p.x + b_stk[c]);
                o.y = tanhf(p.y + b_stk[c + 1]);
                *(float2*)&g_PV[s & 1][b * (NSTACK * ELEM) + c] = o; }
            if (ajt == 0) {
                if (tid < 48) lg[tid] = asum + b_act[ao];
                __syncthreads();
                if (tid < 16) {
                    int bl = tid >> 1, n = tid & 1;
                    float l0 = lg[bl * 6 + n * 3 + 0];
                    float l1 = lg[bl * 6 + n * 3 + 1];
                    float l2 = lg[bl * 6 + n * 3 + 2];
                    float mx = fmaxf(l0, fmaxf(l1, l2));
                    float e0 = expf(l0 - mx), e1 = expf(l1 - mx), e2 = expf(l2 - mx);
                    float inv = 1.f / (e0 + e1 + e2);
                    int sid = (b0 + bl) * 2 + n;
                    g_P[s & 1][sid * 3 + 0] = e0 * inv;
                    g_P[s & 1][sid * 3 + 1] = e1 * inv;
                    g_P[s & 1][sid * 3 + 2] = e2 * inv;
                }
            }
        }

        // ---- grid barrier ----
        __threadfence();
        __syncthreads();
        if (tid == 0) {
            atomicAdd(&g_bar, 1u);
            unsigned int target = (unsigned int)NBLK * (unsigned int)(s + 1);
            while (*((volatile unsigned int*)&g_bar) < target) { }
        }
        __syncthreads();
    }

    // ---- final stack update (step S-1) + write out ----
    {
        int ph = (S_ - 1) & 1;
#pragma unroll
        for (int st = 0; st < 4; st++) {
            int sid = blk * 4 + st;
            int b = sid >> 1, n = sid & 1;
            float pp  = __ldcg(&g_P[ph][sid * 3 + 0]);
            float po  = __ldcg(&g_P[ph][sid * 3 + 1]);
            float pn  = __ldcg(&g_P[ph][sid * 3 + 2]);
            float pvv = __ldcg(&g_PV[ph][b * (NSTACK * ELEM) + n * ELEM + e]);
            float* Sm = stk + st * 4096;
            float* dst = stacks_out + (size_t)sid * 4096;
            float r[18];
#pragma unroll
            for (int i = 0; i < 18; i++) {
                int row = qr - 1 + i;
                r[i] = (row >= 0 && row < SSIZE) ? Sm[row * 64 + e] : 0.f;
            }
#pragma unroll
            for (int i = 0; i < 16; i++) {
                int row = qr + i;
                float v;
                if (row == 0)              v = pp * pvv;
                else if (row == SSIZE - 1) v = emp;
                else v = fmaf(pp, r[i], fmaf(po, r[i + 2], pn * r[i + 1]));
                dst[row * 64 + e] = v;
            }
        }
    }
}

// ---------------- softmax over S + weighted sum -> final_hidden ----------------
__global__ void __launch_bounds__(256) attn_final_k(const float* __restrict__ outputs,
                                                    const int* __restrict__ tokens,
                                                    const float* __restrict__ ba2,
                                                    float* __restrict__ fh) {
    int b = blockIdx.x;
    int tid = threadIdx.x;
    int lane = tid & 31, wid = tid >> 5;
    __shared__ float a_sm[S_];
    __shared__ float rmax[8];
    __shared__ float rsum[8];

    float v = g_spart[0][tid * B_ + b] + g_spart[1][tid * B_ + b] + ba2[0];
    if (tokens[tid * B_ + b] == 0) v = -1e30f;

    float m = v;
#pragma unroll
    for (int off = 16; off > 0; off >>= 1) m = fmaxf(m, __shfl_xor_sync(0xffffffffu, m, off));
    if (lane == 0) rmax[wid] = m;
    __syncthreads();
    float mx = rmax[0];
#pragma unroll
    for (int i = 1; i < 8; i++) mx = fmaxf(mx, rmax[i]);
    float e = expf(v - mx);
    float sum = e;
#pragma unroll
    for (int off = 16; off > 0; off >>= 1) sum += __shfl_xor_sync(0xffffffffu, sum, off);
    if (lane == 0) rsum[wid] = sum;
    __syncthreads();
    float tot = rsum[0];
#pragma unroll
    for (int i = 1; i < 8; i++) tot += rsum[i];
    a_sm[tid] = e / tot;
    __syncthreads();

    float acc = 0.f;
    for (int s2 = 0; s2 < S_; s2++)
        acc += a_sm[s2] * outputs[((size_t)s2 * B_ + b) * H_ + tid];
    fh[b * H_ + tid] = acc;
}

// ---------------- launch ----------------
extern "C" void kernel_launch(void* const* d_in, const int* in_sizes, int n_in,
                              void* d_out, int out_size) {
    const int*   tokens     = (const int*)d_in[0];
    const float* emb        = (const float*)d_in[1];
    const float* W_ih       = (const float*)d_in[2];
    const float* W_hh       = (const float*)d_in[3];
    const float* b_ih       = (const float*)d_in[4];
    const float* b_hh       = (const float*)d_in[5];
    const float* W_act      = (const float*)d_in[6];
    const float* b_act      = (const float*)d_in[7];
    const float* W_stk      = (const float*)d_in[8];
    const float* b_stk      = (const float*)d_in[9];
    const float* empty_elem = (const float*)d_in[10];
    // d_in[11] = W_up, d_in[12] = W_down : shift matrices, hardcoded
    const float* Wa1        = (const float*)d_in[13];
    const float* ba1        = (const float*)d_in[14];
    const float* Wa2        = (const float*)d_in[15];
    const float* ba2        = (const float*)d_in[16];

    float* out     = (float*)d_out;
    float* outputs = out;
    float* fh      = out + (size_t)S_ * B_ * H_;
    float* stacks  = fh + (size_t)B_ * H_;

    float *pWihT, *pWa1T, *pEMB;
    cudaGetSymbolAddress((void**)&pWihT, g_WihT);
    cudaGetSymbolAddress((void**)&pWa1T, g_Wa1T);
    cudaGetSymbolAddress((void**)&pEMB,  g_EMB_GI);

    static int smem_set = 0;
    if (!smem_set) {
        cudaFuncSetAttribute(persist_k, cudaFuncAttributeMaxDynamicSharedMemorySize, SMEM_DYN);
        smem_set = 1;
    }

    // launches 0-3: prep
    prep_a<<<(H3 * H_ + 255) / 256, 256>>>(W_ih);
    prep_b<<<(H3 * H_ + 255) / 256, 256>>>(W_hh);
    prep_c<<<(H_ * H_ + 255) / 256, 256>>>(W_stk, Wa1);
    prep_d<<<(B_ * H_ + 255) / 256, 256>>>();

    // launch 4: EMB_GI = emb @ W_ih^T + b_ih  (32000 x 768)
    {
        dim3 grid(H3 / 128, VOCAB_ / 128);
        sgemm128_k<false><<<grid, 256>>>(emb, pWihT, b_ih, pEMB, nullptr, VOCAB_, H3, H_);
    }

    // launch 5: the whole recurrence in ONE persistent kernel
    persist_k<<<NBLK, 256, SMEM_DYN>>>(tokens, b_ih, b_hh, W_act, b_act, b_stk,
                                       empty_elem, outputs, stacks);

    // launch 6: attention partials (fused tanh(outputs@Wa1^T+ba1)@Wa2^T)
    {
        dim3 grid(H_ / 128, (S_ * B_) / 128);
        sgemm128_k<true><<<grid, 256>>>(outputs, pWa1T, ba1, nullptr, Wa2, S_ * B_, H_, H_);
    }
    // launch 7: softmax + weighted sum
    attn_final_k<<<B_, 256>>>(outputs, tokens, ba2, fh);
}

// round 6
// speedup vs baseline: 1.0454x; 1.0454x over previous
#include <cuda_runtime.h>
#include <math.h>

#define S_ 256
#define B_ 512
#define H_ 256
#define H3 768
#define VOCAB_ 32000
#define NSTACK 2
#define SSIZE 64
#define ELEM 64
#define NBLK 256

// ---------------- device scratch (static, no allocation) ----------------
__device__ float g_EMB_GI[VOCAB_ * H3];       // emb @ W_ih^T + b_ih
__device__ float g_WihT[H_ * H3];             // [k][n]
__device__ float g_WhhT[H_ * H3];             // [k][n]
__device__ float g_WstkT[H_ * (NSTACK * ELEM)];
__device__ float g_Wa1T[H_ * H_];
__device__ float g_h[2][B_ * H_];             // hidden ping-pong
__device__ float g_PV[2][B_ * NSTACK * ELEM]; // push_vals ping-pong
__device__ float g_P[2][B_ * NSTACK * 3];     // act probs ping-pong
__device__ float g_spart[2][S_ * B_];         // attention score partials
__device__ unsigned int g_bar;                // grid barrier counter

__device__ __forceinline__ float sigmoidf_(float x) { return 1.f / (1.f + expf(-x)); }

// ---------------- packed f32x2 helpers ----------------
__device__ __forceinline__ unsigned long long pack2(float x) {
    unsigned long long d;
    unsigned int u = __float_as_uint(x);
    asm("mov.b64 %0, {%1, %1};" : "=l"(d) : "r"(u));
    return d;
}
__device__ __forceinline__ void fma2(unsigned long long& d, unsigned long long a,
                                     unsigned long long b) {
    asm("fma.rn.f32x2 %0, %1, %2, %0;" : "+l"(d) : "l"(a), "l"(b));
}
__device__ __forceinline__ float2 unpack2(unsigned long long v) {
    unsigned int lo, hi;
    asm("mov.b64 {%0, %1}, %2;" : "=r"(lo), "=r"(hi) : "l"(v));
    return make_float2(__uint_as_float(lo), __uint_as_float(hi));
}

// ---------------- prep kernels (split so persist = launch #5 for ncu) ----------------
__global__ void prep_a(const float* __restrict__ W_ih) {
    int idx = blockIdx.x * 256 + threadIdx.x;
    if (idx < H3 * H_) { int r = idx % H3, c = idx / H3; g_WihT[idx] = W_ih[r * H_ + c]; }
}
__global__ void prep_b(const float* __restrict__ W_hh) {
    int idx = blockIdx.x * 256 + threadIdx.x;
    if (idx < H3 * H_) { int r = idx % H3, c = idx / H3; g_WhhT[idx] = W_hh[r * H_ + c]; }
}
__global__ void prep_c(const float* __restrict__ W_stk, const float* __restrict__ Wa1) {
    int idx = blockIdx.x * 256 + threadIdx.x;
    if (idx < (NSTACK * ELEM) * H_) {
        int r = idx % (NSTACK * ELEM), c = idx / (NSTACK * ELEM);
        g_WstkT[idx] = W_stk[r * H_ + c];
    }
    if (idx < H_ * H_) { int r = idx % H_, c = idx / H_; g_Wa1T[idx] = Wa1[r * H_ + c]; }
}
__global__ void prep_d() {
    int idx = blockIdx.x * 256 + threadIdx.x;
    if (idx < B_ * H_) g_h[0][idx] = 0.f;
    if (idx == 0) g_bar = 0u;
}

// ---------------- 128x128x16 SGEMM with f32x2 ----------------
template <bool SCORE>
__global__ void __launch_bounds__(256) sgemm128_k(
    const float* __restrict__ A, const float* __restrict__ Bm,
    const float* __restrict__ bias, float* __restrict__ C,
    const float* __restrict__ Wa2,
    int M, int N, int K)
{
    __shared__ __align__(16) float As[16][128];   // [k][m]
    __shared__ __align__(16) float Bs[16][128];   // [k][n]
    int tid = threadIdx.x;
    int m0 = blockIdx.y * 128, n0 = blockIdx.x * 128;
    int tx = tid & 15, ty = tid >> 4;

    unsigned long long acc[2][2][4][2];
#pragma unroll
    for (int a = 0; a < 2; a++)
#pragma unroll
        for (int b = 0; b < 2; b++)
#pragma unroll
            for (int c = 0; c < 4; c++) { acc[a][b][c][0] = 0ull; acc[a][b][c][1] = 0ull; }

    for (int k0 = 0; k0 < K; k0 += 16) {
#pragma unroll
        for (int i = 0; i < 2; i++) {
            int f = tid * 2 + i;
            int arow = f >> 2, aq = (f & 3) * 4;
            float4 v = *(const float4*)&A[(size_t)(m0 + arow) * K + k0 + aq];
            As[aq + 0][arow] = v.x; As[aq + 1][arow] = v.y;
            As[aq + 2][arow] = v.z; As[aq + 3][arow] = v.w;
            int brow = f >> 5, bc = (f & 31) * 4;
            *(float4*)&Bs[brow][bc] = *(const float4*)&Bm[(size_t)(k0 + brow) * N + n0 + bc];
        }
        __syncthreads();
#pragma unroll
        for (int kk = 0; kk < 16; kk++) {
            float4 a0 = *(float4*)&As[kk][ty * 4];
            float4 a1 = *(float4*)&As[kk][ty * 4 + 64];
            unsigned long long ap[2][4];
            ap[0][0] = pack2(a0.x); ap[0][1] = pack2(a0.y);
            ap[0][2] = pack2(a0.z); ap[0][3] = pack2(a0.w);
            ap[1][0] = pack2(a1.x); ap[1][1] = pack2(a1.y);
            ap[1][2] = pack2(a1.z); ap[1][3] = pack2(a1.w);
            ulonglong2 b0 = *(ulonglong2*)&Bs[kk][tx * 4];
            ulonglong2 b1 = *(ulonglong2*)&Bs[kk][tx * 4 + 64];
#pragma unroll
            for (int ic = 0; ic < 2; ic++)
#pragma unroll
                for (int i = 0; i < 4; i++) {
                    fma2(acc[ic][0][i][0], ap[ic][i], b0.x);
                    fma2(acc[ic][0][i][1], ap[ic][i], b0.y);
                    fma2(acc[ic][1][i][0], ap[ic][i], b1.x);
                    fma2(acc[ic][1][i][1], ap[ic][i], b1.y);
                }
        }
        __syncthreads();
    }

    if (!SCORE) {
#pragma unroll
        for (int ic = 0; ic < 2; ic++)
#pragma unroll
            for (int i = 0; i < 4; i++) {
                int m = m0 + ic * 64 + ty * 4 + i;
#pragma unroll
                for (int jc = 0; jc < 2; jc++) {
                    int n = n0 + jc * 64 + tx * 4;
                    float2 p0 = unpack2(acc[ic][jc][i][0]);
                    float2 p1 = unpack2(acc[ic][jc][i][1]);
                    float4 o;
                    o.x = p0.x + bias[n + 0];
                    o.y = p0.y + bias[n + 1];
                    o.z = p1.x + bias[n + 2];
                    o.w = p1.y + bias[n + 3];
                    *(float4*)&C[(size_t)m * N + n] = o;
                }
            }
    } else {
        float4 bb[2], ww[2];
#pragma unroll
        for (int jc = 0; jc < 2; jc++) {
            int n = n0 + jc * 64 + tx * 4;
            bb[jc] = *(const float4*)&bias[n];
            ww[jc] = *(const float4*)&Wa2[n];
        }
#pragma unroll
        for (int ic = 0; ic < 2; ic++)
#pragma unroll
            for (int i = 0; i < 4; i++) {
                float p = 0.f;
#pragma unroll
                for (int jc = 0; jc < 2; jc++) {
                    float2 p0 = unpack2(acc[ic][jc][i][0]);
                    float2 p1 = unpack2(acc[ic][jc][i][1]);
                    p += tanhf(p0.x + bb[jc].x) * ww[jc].x;
                    p += tanhf(p0.y + bb[jc].y) * ww[jc].y;
                    p += tanhf(p1.x + bb[jc].z) * ww[jc].z;
                    p += tanhf(p1.y + bb[jc].w) * ww[jc].w;
                }
#pragma unroll
                for (int off = 8; off > 0; off >>= 1)
                    p += __shfl_xor_sync(0xffffffffu, p, off);
                if (tx == 0) {
                    int m = m0 + ic * 64 + ty * 4 + i;
                    g_spart[blockIdx.x][m] = p;
                }
            }
    }
}

// ---------------- persistent recurrence kernel ----------------
// 256 blocks x 256 threads, all co-resident (2/SM). Grid barrier per step.
// blocks [0,128):   GRU tile: 16 batches x 64 h-cols x 3 gates
// blocks [128,256): AUX tile: 8 batches x 64 pv-cols; jt==0 also ACT (probs)
// every block owns 4 stacks in SMEM for the whole recurrence.
// SMEM: stacks 65536B | GRU: As 32*18*4=2304B, Bs 3*32*68*4=26112B (AUX aliases)
#define SMEM_DYN (65536 + 2304 + 26112)

__global__ void __launch_bounds__(256, 2) persist_k(
    const int* __restrict__ tokens,
    const float* __restrict__ b_ih,
    const float* __restrict__ b_hh,
    const float* __restrict__ W_act,
    const float* __restrict__ b_act,
    const float* __restrict__ b_stk,
    const float* __restrict__ empty_elem,
    float* __restrict__ outputs,
    float* __restrict__ stacks_out)
{
    extern __shared__ __align__(16) float smem[];
    float* stk = smem;                 // 4 * 4096
    float* gA  = smem + 16384;         // [k(32)][m(16)+pad2]
    float* gB  = gA + 32 * 18;         // [3][32][64+pad4]
    float* aA  = gA;                   // [k(32)][m(8)+pad2]
    float* aB  = aA + 320;             // [32][64+pad4]
    float* lg  = aB + 32 * 68;         // 48 logits

    int tid = threadIdx.x;
    int blk = blockIdx.x;
    int e   = tid & 63;
    int qr  = (tid >> 6) * 16;
    int tx  = tid & 31, ty = tid >> 5;
    float emp = empty_elem[e];

    // init this block's 4 stacks to empty
    for (int i = tid; i < 4 * 4096; i += 256) stk[i] = empty_elem[i & 63];

    const bool isGRU = blk < 128;
    int mt = blk >> 2, jt = blk & 3;          // GRU mapping
    int ai = blk - 128, amt = ai >> 1, ajt = ai & 1;  // AUX mapping

    for (int s = 0; s < S_; s++) {
        // ---- stack update for step s-1 (SMEM-resident) ----
        if (s > 0) {
            int ph = (s - 1) & 1;
#pragma unroll
            for (int st = 0; st < 4; st++) {
                int sid = blk * 4 + st;
                int b = sid >> 1, n = sid & 1;
                float pp  = __ldcg(&g_P[ph][sid * 3 + 0]);
                float po  = __ldcg(&g_P[ph][sid * 3 + 1]);
                float pn  = __ldcg(&g_P[ph][sid * 3 + 2]);
                float pvv = __ldcg(&g_PV[ph][b * (NSTACK * ELEM) + n * ELEM + e]);
                float* Sm = stk + st * 4096;
                float r[18];
#pragma unroll
                for (int i = 0; i < 18; i++) {
                    int row = qr - 1 + i;
                    r[i] = (row >= 0 && row < SSIZE) ? Sm[row * 64 + e] : 0.f;
                }
                __syncthreads();
#pragma unroll
                for (int i = 0; i < 16; i++) {
                    int row = qr + i;
                    float v;
                    if (row == 0)              v = pp * pvv;
                    else if (row == SSIZE - 1) v = emp;
                    else v = fmaf(pp, r[i], fmaf(po, r[i + 2], pn * r[i + 1]));
                    Sm[row * 64 + e] = v;
                }
                __syncthreads();
            }
        }

        const float* hin = g_h[s & 1];
        if (isGRU) {
            float* hout = g_h[(s + 1) & 1];
            int b0 = mt * 16, j0 = jt * 64;
            unsigned long long acc[3][2] = {{0ull,0ull},{0ull,0ull},{0ull,0ull}};
            for (int k0 = 0; k0 < H_; k0 += 32) {
                {   int m = tid >> 4, k2 = (tid & 15) * 2;
                    float2 v = __ldcg((const float2*)&hin[(b0 + m) * H_ + k0 + k2]);
                    gA[k2 * 18 + m] = v.x; gA[(k2 + 1) * 18 + m] = v.y; }
                {   int rI = tid >> 3, c = (tid & 7) * 8;
                    const float* src = &g_WhhT[(size_t)(k0 + rI) * H3 + j0 + c];
#pragma unroll
                    for (int g = 0; g < 3; g++) {
                        *(float4*)&gB[(g * 32 + rI) * 68 + c]     = *(const float4*)(src + g * H_);
                        *(float4*)&gB[(g * 32 + rI) * 68 + c + 4] = *(const float4*)(src + g * H_ + 4);
                    }
                }
                __syncthreads();
#pragma unroll
                for (int kk = 0; kk < 32; kk++) {
                    float2 av = *(float2*)&gA[kk * 18 + ty * 2];
                    unsigned long long a0 = pack2(av.x), a1 = pack2(av.y);
#pragma unroll
                    for (int g = 0; g < 3; g++) {
                        unsigned long long bv = *(unsigned long long*)&gB[(g * 32 + kk) * 68 + tx * 2];
                        fma2(acc[g][0], a0, bv);
                        fma2(acc[g][1], a1, bv);
                    }
                }
                __syncthreads();
            }
            int j = j0 + tx * 2;
            float2 br = *(const float2*)&b_hh[j];
            float2 bz = *(const float2*)&b_hh[H_ + j];
            float2 bn = *(const float2*)&b_hh[2 * H_ + j];
#pragma unroll
            for (int mi = 0; mi < 2; mi++) {
                int b = b0 + ty * 2 + mi;
                int tok = tokens[s * B_ + b];
                const float* gi = (tok == 0) ? b_ih : (g_EMB_GI + (size_t)tok * H3);
                float2 gr = *(const float2*)&gi[j];
                float2 gz = *(const float2*)&gi[H_ + j];
                float2 gn = *(const float2*)&gi[2 * H_ + j];
                float2 hp = __ldcg((const float2*)&hin[b * H_ + j]);
                float2 R = unpack2(acc[0][mi]);
                float2 Z = unpack2(acc[1][mi]);
                float2 N = unpack2(acc[2][mi]);
                float2 o;
                {   float rr = sigmoidf_(gr.x + R.x + br.x);
                    float zz = sigmoidf_(gz.x + Z.x + bz.x);
                    float nn = tanhf(gn.x + rr * (N.x + bn.x));
                    o.x = (1.f - zz) * nn + zz * hp.x; }
                {   float rr = sigmoidf_(gr.y + R.y + br.y);
                    float zz = sigmoidf_(gz.y + Z.y + bz.y);
                    float nn = tanhf(gn.y + rr * (N.y + bn.y));
                    o.y = (1.f - zz) * nn + zz * hp.y; }
                *(float2*)&hout[b * H_ + j] = o;
                *(float2*)&outputs[((size_t)s * B_ + b) * H_ + j] = o;
            }
        } else {
            int b0 = amt * 8, c0 = ajt * 64;
            unsigned long long acc = 0ull;
            float asum = 0.f;
            bool act = (ajt == 0) && (tid < 48);
            int abl = tid / 6, ao = tid % 6;
            for (int k0 = 0; k0 < H_; k0 += 32) {
                {   int m = tid >> 5, kk = tid & 31;
                    aA[kk * 10 + m] = __ldcg(&hin[(b0 + m) * H_ + k0 + kk]); }
                {   int rI = tid >> 3, c = (tid & 7) * 8;
                    const float* src = &g_WstkT[(size_t)(k0 + rI) * (NSTACK * ELEM) + c0 + c];
                    *(float4*)&aB[rI * 68 + c]     = *(const float4*)(src);
                    *(float4*)&aB[rI * 68 + c + 4] = *(const float4*)(src + 4);
                }
                __syncthreads();
#pragma unroll
                for (int kk = 0; kk < 32; kk++) {
                    unsigned long long ap = pack2(aA[kk * 10 + ty]);
                    unsigned long long bv = *(unsigned long long*)&aB[kk * 68 + tx * 2];
                    fma2(acc, ap, bv);
                }
                if (act) {
#pragma unroll 8
                    for (int kk = 0; kk < 32; kk++)
                        asum = fmaf(aA[kk * 10 + abl], W_act[ao * H_ + k0 + kk], asum);
                }
                __syncthreads();
            }
            {   int b = b0 + ty;
                int c = c0 + tx * 2;
                float2 p = unpack2(acc);
                float2 o;
                o.x = tanhf(p.x + b_stk[c]);
                o.y = tanhf(p.y + b_stk[c + 1]);
                *(float2*)&g_PV[s & 1][b * (NSTACK * ELEM) + c] = o; }
            if (ajt == 0) {
                if (tid < 48) lg[tid] = asum + b_act[ao];
                __syncthreads();
                if (tid < 16) {
                    int bl = tid >> 1, n = tid & 1;
                    float l0 = lg[bl * 6 + n * 3 + 0];
                    float l1 = lg[bl * 6 + n * 3 + 1];
                    float l2 = lg[bl * 6 + n * 3 + 2];
                    float mx = fmaxf(l0, fmaxf(l1, l2));
                    float e0 = expf(l0 - mx), e1 = expf(l1 - mx), e2 = expf(l2 - mx);
                    float inv = 1.f / (e0 + e1 + e2);
                    int sid = (b0 + bl) * 2 + n;
                    g_P[s & 1][sid * 3 + 0] = e0 * inv;
                    g_P[s & 1][sid * 3 + 1] = e1 * inv;
                    g_P[s & 1][sid * 3 + 2] = e2 * inv;
                }
            }
        }

        // ---- grid barrier ----
        __threadfence();
        __syncthreads();
        if (tid == 0) {
            atomicAdd(&g_bar, 1u);
            unsigned int target = (unsigned int)NBLK * (unsigned int)(s + 1);
            while (*((volatile unsigned int*)&g_bar) < target) { }
        }
        __syncthreads();
    }

    // ---- final stack update (step S-1) + write out ----
    {
        int ph = (S_ - 1) & 1;
#pragma unroll
        for (int st = 0; st < 4; st++) {
            int sid = blk * 4 + st;
            int b = sid >> 1, n = sid & 1;
            float pp  = __ldcg(&g_P[ph][sid * 3 + 0]);
            float po  = __ldcg(&g_P[ph][sid * 3 + 1]);
            float pn  = __ldcg(&g_P[ph][sid * 3 + 2]);
            float pvv = __ldcg(&g_PV[ph][b * (NSTACK * ELEM) + n * ELEM + e]);
            float* Sm = stk + st * 4096;
            float* dst = stacks_out + (size_t)sid * 4096;
            float r[18];
#pragma unroll
            for (int i = 0; i < 18; i++) {
                int row = qr - 1 + i;
                r[i] = (row >= 0 && row < SSIZE) ? Sm[row * 64 + e] : 0.f;
            }
#pragma unroll
            for (int i = 0; i < 16; i++) {
                int row = qr + i;
                float v;
                if (row == 0)              v = pp * pvv;
                else if (row == SSIZE - 1) v = emp;
                else v = fmaf(pp, r[i], fmaf(po, r[i + 2], pn * r[i + 1]));
                dst[row * 64 + e] = v;
            }
        }
    }
}

// ---------------- softmax over S + weighted sum -> final_hidden ----------------
__global__ void __launch_bounds__(256) attn_final_k(const float* __restrict__ outputs,
                                                    const int* __restrict__ tokens,
                                                    const float* __restrict__ ba2,
                                                    float* __restrict__ fh) {
    int b = blockIdx.x;
    int tid = threadIdx.x;
    int lane = tid & 31, wid = tid >> 5;
    __shared__ float a_sm[S_];
    __shared__ float rmax[8];
    __shared__ float rsum[8];

    float v = g_spart[0][tid * B_ + b] + g_spart[1][tid * B_ + b] + ba2[0];
    if (tokens[tid * B_ + b] == 0) v = -1e30f;

    float m = v;
#pragma unroll
    for (int off = 16; off > 0; off >>= 1) m = fmaxf(m, __shfl_xor_sync(0xffffffffu, m, off));
    if (lane == 0) rmax[wid] = m;
    __syncthreads();
    float mx = rmax[0];
#pragma unroll
    for (int i = 1; i < 8; i++) mx = fmaxf(mx, rmax[i]);
    float e = expf(v - mx);
    float sum = e;
#pragma unroll
    for (int off = 16; off > 0; off >>= 1) sum += __shfl_xor_sync(0xffffffffu, sum, off);
    if (lane == 0) rsum[wid] = sum;
    __syncthreads();
    float tot = rsum[0];
#pragma unroll
    for (int i = 1; i < 8; i++) tot += rsum[i];
    a_sm[tid] = e / tot;
    __syncthreads();

    float acc = 0.f;
    for (int s2 = 0; s2 < S_; s2++)
        acc += a_sm[s2] * outputs[((size_t)s2 * B_ + b) * H_ + tid];
    fh[b * H_ + tid] = acc;
}

// ---------------- launch ----------------
extern "C" void kernel_launch(void* const* d_in, const int* in_sizes, int n_in,
                              void* d_out, int out_size) {
    const int*   tokens     = (const int*)d_in[0];
    const float* emb        = (const float*)d_in[1];
    const float* W_ih       = (const float*)d_in[2];
    const float* W_hh       = (const float*)d_in[3];
    const float* b_ih       = (const float*)d_in[4];
    const float* b_hh       = (const float*)d_in[5];
    const float* W_act      = (const float*)d_in[6];
    const float* b_act      = (const float*)d_in[7];
    const float* W_stk      = (const float*)d_in[8];
    const float* b_stk      = (const float*)d_in[9];
    const float* empty_elem = (const float*)d_in[10];
    // d_in[11] = W_up, d_in[12] = W_down : shift matrices, hardcoded
    const float* Wa1        = (const float*)d_in[13];
    const float* ba1        = (const float*)d_in[14];
    const float* Wa2        = (const float*)d_in[15];
    const float* ba2        = (const float*)d_in[16];

    float* out     = (float*)d_out;
    float* outputs = out;
    float* fh      = out + (size_t)S_ * B_ * H_;
    float* stacks  = fh + (size_t)B_ * H_;

    float *pWihT, *pWa1T, *pEMB;
    cudaGetSymbolAddress((void**)&pWihT, g_WihT);
    cudaGetSymbolAddress((void**)&pWa1T, g_Wa1T);
    cudaGetSymbolAddress((void**)&pEMB,  g_EMB_GI);

    static int smem_set = 0;
    if (!smem_set) {
        cudaFuncSetAttribute(persist_k, cudaFuncAttributeMaxDynamicSharedMemorySize, SMEM_DYN);
        smem_set = 1;
    }

    // launches 0-3: prep
    prep_a<<<(H3 * H_ + 255) / 256, 256>>>(W_ih);
    prep_b<<<(H3 * H_ + 255) / 256, 256>>>(W_hh);
    prep_c<<<(H_ * H_ + 255) / 256, 256>>>(W_stk, Wa1);
    prep_d<<<(B_ * H_ + 255) / 256, 256>>>();

    // launch 4: EMB_GI = emb @ W_ih^T + b_ih  (32000 x 768)
    {
        dim3 grid(H3 / 128, VOCAB_ / 128);
        sgemm128_k<false><<<grid, 256>>>(emb, pWihT, b_ih, pEMB, nullptr, VOCAB_, H3, H_);
    }

    // launch 5: the whole recurrence in ONE persistent kernel
    persist_k<<<NBLK, 256, SMEM_DYN>>>(tokens, b_ih, b_hh, W_act, b_act, b_stk,
                                       empty_elem, outputs, stacks);

    // launch 6: attention partials (fused tanh(outputs@Wa1^T+ba1)@Wa2^T)
    {
        dim3 grid(H_ / 128, (S_ * B_) / 128);
        sgemm128_k<true><<<grid, 256>>>(outputs, pWa1T, ba1, nullptr, Wa2, S_ * B_, H_, H_);
    }
    // launch 7: softmax + weighted sum
    attn_final_k<<<B_, 256>>>(outputs, tokens, ba2, fh);
}

// round 7
// speedup vs baseline: 1.0468x; 1.0013x over previous
#include <cuda_runtime.h>
#include <math.h>

#define S_ 256
#define B_ 512
#define H_ 256
#define H3 768
#define VOCAB_ 32000
#define NSTACK 2
#define SSIZE 64
#define ELEM 64
#define NBLK 256

// ---------------- device scratch (static, no allocation) ----------------
__device__ float g_EMB_GI[VOCAB_ * H3];       // emb @ W_ih^T + b_ih
__device__ float g_WihT[H_ * H3];             // [k][n]
__device__ float g_WhhT[H_ * H3];             // [k][n]
__device__ float g_WstkT[H_ * (NSTACK * ELEM)];
__device__ float g_Wa1T[H_ * H_];
__device__ float g_h[2][B_ * H_];             // hidden ping-pong
__device__ float g_PV[2][B_ * NSTACK * ELEM]; // push_vals ping-pong
__device__ float g_P[2][B_ * NSTACK * 3];     // act probs ping-pong
__device__ float g_spart[2][S_ * B_];         // attention score partials
__device__ unsigned int g_bar;                // grid barrier counter

__device__ __forceinline__ float sigmoidf_(float x) { return 1.f / (1.f + expf(-x)); }

// ---------------- packed f32x2 helpers ----------------
__device__ __forceinline__ unsigned long long pack2(float x) {
    unsigned long long d;
    unsigned int u = __float_as_uint(x);
    asm("mov.b64 %0, {%1, %1};" : "=l"(d) : "r"(u));
    return d;
}
__device__ __forceinline__ void fma2(unsigned long long& d, unsigned long long a,
                                     unsigned long long b) {
    asm("fma.rn.f32x2 %0, %1, %2, %0;" : "+l"(d) : "l"(a), "l"(b));
}
__device__ __forceinline__ float2 unpack2(unsigned long long v) {
    unsigned int lo, hi;
    asm("mov.b64 {%0, %1}, %2;" : "=r"(lo), "=r"(hi) : "l"(v));
    return make_float2(__uint_as_float(lo), __uint_as_float(hi));
}

// ---------------- prep kernels (split so persist = launch #5 for ncu) ----------------
__global__ void prep_a(const float* __restrict__ W_ih) {
    int idx = blockIdx.x * 256 + threadIdx.x;
    if (idx < H3 * H_) { int r = idx % H3, c = idx / H3; g_WihT[idx] = W_ih[r * H_ + c]; }
}
__global__ void prep_b(const float* __restrict__ W_hh) {
    int idx = blockIdx.x * 256 + threadIdx.x;
    if (idx < H3 * H_) { int r = idx % H3, c = idx / H3; g_WhhT[idx] = W_hh[r * H_ + c]; }
}
__global__ void prep_c(const float* __restrict__ W_stk, const float* __restrict__ Wa1) {
    int idx = blockIdx.x * 256 + threadIdx.x;
    if (idx < (NSTACK * ELEM) * H_) {
        int r = idx % (NSTACK * ELEM), c = idx / (NSTACK * ELEM);
        g_WstkT[idx] = W_stk[r * H_ + c];
    }
    if (idx < H_ * H_) { int r = idx % H_, c = idx / H_; g_Wa1T[idx] = Wa1[r * H_ + c]; }
}
__global__ void prep_d() {
    int idx = blockIdx.x * 256 + threadIdx.x;
    if (idx < B_ * H_) g_h[0][idx] = 0.f;
    if (idx == 0) g_bar = 0u;
}

// ---------------- 128x128x16 SGEMM with f32x2 ----------------
template <bool SCORE>
__global__ void __launch_bounds__(256) sgemm128_k(
    const float* __restrict__ A, const float* __restrict__ Bm,
    const float* __restrict__ bias, float* __restrict__ C,
    const float* __restrict__ Wa2,
    int M, int N, int K)
{
    __shared__ __align__(16) float As[16][128];   // [k][m]
    __shared__ __align__(16) float Bs[16][128];   // [k][n]
    int tid = threadIdx.x;
    int m0 = blockIdx.y * 128, n0 = blockIdx.x * 128;
    int tx = tid & 15, ty = tid >> 4;

    unsigned long long acc[2][2][4][2];
#pragma unroll
    for (int a = 0; a < 2; a++)
#pragma unroll
        for (int b = 0; b < 2; b++)
#pragma unroll
            for (int c = 0; c < 4; c++) { acc[a][b][c][0] = 0ull; acc[a][b][c][1] = 0ull; }

    for (int k0 = 0; k0 < K; k0 += 16) {
#pragma unroll
        for (int i = 0; i < 2; i++) {
            int f = tid * 2 + i;
            int arow = f >> 2, aq = (f & 3) * 4;
            float4 v = *(const float4*)&A[(size_t)(m0 + arow) * K + k0 + aq];
            As[aq + 0][arow] = v.x; As[aq + 1][arow] = v.y;
            As[aq + 2][arow] = v.z; As[aq + 3][arow] = v.w;
            int brow = f >> 5, bc = (f & 31) * 4;
            *(float4*)&Bs[brow][bc] = *(const float4*)&Bm[(size_t)(k0 + brow) * N + n0 + bc];
        }
        __syncthreads();
#pragma unroll
        for (int kk = 0; kk < 16; kk++) {
            float4 a0 = *(float4*)&As[kk][ty * 4];
            float4 a1 = *(float4*)&As[kk][ty * 4 + 64];
            unsigned long long ap[2][4];
            ap[0][0] = pack2(a0.x); ap[0][1] = pack2(a0.y);
            ap[0][2] = pack2(a0.z); ap[0][3] = pack2(a0.w);
            ap[1][0] = pack2(a1.x); ap[1][1] = pack2(a1.y);
            ap[1][2] = pack2(a1.z); ap[1][3] = pack2(a1.w);
            ulonglong2 b0 = *(ulonglong2*)&Bs[kk][tx * 4];
            ulonglong2 b1 = *(ulonglong2*)&Bs[kk][tx * 4 + 64];
#pragma unroll
            for (int ic = 0; ic < 2; ic++)
#pragma unroll
                for (int i = 0; i < 4; i++) {
                    fma2(acc[ic][0][i][0], ap[ic][i], b0.x);
                    fma2(acc[ic][0][i][1], ap[ic][i], b0.y);
                    fma2(acc[ic][1][i][0], ap[ic][i], b1.x);
                    fma2(acc[ic][1][i][1], ap[ic][i], b1.y);
                }
        }
        __syncthreads();
    }

    if (!SCORE) {
#pragma unroll
        for (int ic = 0; ic < 2; ic++)
#pragma unroll
            for (int i = 0; i < 4; i++) {
                int m = m0 + ic * 64 + ty * 4 + i;
#pragma unroll
                for (int jc = 0; jc < 2; jc++) {
                    int n = n0 + jc * 64 + tx * 4;
                    float2 p0 = unpack2(acc[ic][jc][i][0]);
                    float2 p1 = unpack2(acc[ic][jc][i][1]);
                    float4 o;
                    o.x = p0.x + bias[n + 0];
                    o.y = p0.y + bias[n + 1];
                    o.z = p1.x + bias[n + 2];
                    o.w = p1.y + bias[n + 3];
                    *(float4*)&C[(size_t)m * N + n] = o;
                }
            }
    } else {
        float4 bb[2], ww[2];
#pragma unroll
        for (int jc = 0; jc < 2; jc++) {
            int n = n0 + jc * 64 + tx * 4;
            bb[jc] = *(const float4*)&bias[n];
            ww[jc] = *(const float4*)&Wa2[n];
        }
#pragma unroll
        for (int ic = 0; ic < 2; ic++)
#pragma unroll
            for (int i = 0; i < 4; i++) {
                float p = 0.f;
#pragma unroll
                for (int jc = 0; jc < 2; jc++) {
                    float2 p0 = unpack2(acc[ic][jc][i][0]);
                    float2 p1 = unpack2(acc[ic][jc][i][1]);
                    p += tanhf(p0.x + bb[jc].x) * ww[jc].x;
                    p += tanhf(p0.y + bb[jc].y) * ww[jc].y;
                    p += tanhf(p1.x + bb[jc].z) * ww[jc].z;
                    p += tanhf(p1.y + bb[jc].w) * ww[jc].w;
                }
#pragma unroll
                for (int off = 8; off > 0; off >>= 1)
                    p += __shfl_xor_sync(0xffffffffu, p, off);
                if (tx == 0) {
                    int m = m0 + ic * 64 + ty * 4 + i;
                    g_spart[blockIdx.x][m] = p;
                }
            }
    }
}

// ---------------- persistent recurrence kernel ----------------
// 256 blocks x 256 threads, all co-resident (2/SM). Grid barrier per step.
// blocks [0,128):   GRU tile: 16 batches x 64 h-cols x 3 gates
// blocks [128,256): AUX tile: 8 batches x 64 pv-cols; jt==0 also ACT (probs)
// every block owns 4 stacks in SMEM for the whole recurrence.
// SMEM: stacks 65536B | GRU: As 32*18*4=2304B, Bs 3*32*68*4=26112B (AUX aliases)
#define SMEM_DYN (65536 + 2304 + 26112)

__global__ void __launch_bounds__(256, 2) persist_k(
    const int* __restrict__ tokens,
    const float* __restrict__ b_ih,
    const float* __restrict__ b_hh,
    const float* __restrict__ W_act,
    const float* __restrict__ b_act,
    const float* __restrict__ b_stk,
    const float* __restrict__ empty_elem,
    float* __restrict__ outputs,
    float* __restrict__ stacks_out)
{
    extern __shared__ __align__(16) float smem[];
    float* stk = smem;                 // 4 * 4096
    float* gA  = smem + 16384;         // [k(32)][m(16)+pad2]
    float* gB  = gA + 32 * 18;         // [3][32][64+pad4]
    float* aA  = gA;                   // [k(32)][m(8)+pad2]
    float* aB  = aA + 320;             // [32][64+pad4]
    float* lg  = aB + 32 * 68;         // 48 logits

    int tid = threadIdx.x;
    int blk = blockIdx.x;
    int e   = tid & 63;
    int qr  = (tid >> 6) * 16;
    int tx  = tid & 31, ty = tid >> 5;
    float emp = empty_elem[e];

    // init this block's 4 stacks to empty
    for (int i = tid; i < 4 * 4096; i += 256) stk[i] = empty_elem[i & 63];

    const bool isGRU = blk < 128;
    int mt = blk >> 2, jt = blk & 3;          // GRU mapping
    int ai = blk - 128, amt = ai >> 1, ajt = ai & 1;  // AUX mapping

    for (int s = 0; s < S_; s++) {
        // ---- stack update for step s-1 (SMEM-resident) ----
        if (s > 0) {
            int ph = (s - 1) & 1;
#pragma unroll
            for (int st = 0; st < 4; st++) {
                int sid = blk * 4 + st;
                int b = sid >> 1, n = sid & 1;
                float pp  = __ldcg(&g_P[ph][sid * 3 + 0]);
                float po  = __ldcg(&g_P[ph][sid * 3 + 1]);
                float pn  = __ldcg(&g_P[ph][sid * 3 + 2]);
                float pvv = __ldcg(&g_PV[ph][b * (NSTACK * ELEM) + n * ELEM + e]);
                float* Sm = stk + st * 4096;
                float r[18];
#pragma unroll
                for (int i = 0; i < 18; i++) {
                    int row = qr - 1 + i;
                    r[i] = (row >= 0 && row < SSIZE) ? Sm[row * 64 + e] : 0.f;
                }
                __syncthreads();
#pragma unroll
                for (int i = 0; i < 16; i++) {
                    int row = qr + i;
                    float v;
                    if (row == 0)              v = pp * pvv;
                    else if (row == SSIZE - 1) v = emp;
                    else v = fmaf(pp, r[i], fmaf(po, r[i + 2], pn * r[i + 1]));
                    Sm[row * 64 + e] = v;
                }
                __syncthreads();
            }
        }

        const float* hin = g_h[s & 1];
        if (isGRU) {
            float* hout = g_h[(s + 1) & 1];
            int b0 = mt * 16, j0 = jt * 64;
            unsigned long long acc[3][2] = {{0ull,0ull},{0ull,0ull},{0ull,0ull}};
            for (int k0 = 0; k0 < H_; k0 += 32) {
                {   int m = tid >> 4, k2 = (tid & 15) * 2;
                    float2 v = __ldcg((const float2*)&hin[(b0 + m) * H_ + k0 + k2]);
                    gA[k2 * 18 + m] = v.x; gA[(k2 + 1) * 18 + m] = v.y; }
                {   int rI = tid >> 3, c = (tid & 7) * 8;
                    const float* src = &g_WhhT[(size_t)(k0 + rI) * H3 + j0 + c];
#pragma unroll
                    for (int g = 0; g < 3; g++) {
                        *(float4*)&gB[(g * 32 + rI) * 68 + c]     = *(const float4*)(src + g * H_);
                        *(float4*)&gB[(g * 32 + rI) * 68 + c + 4] = *(const float4*)(src + g * H_ + 4);
                    }
                }
                __syncthreads();
#pragma unroll
                for (int kk = 0; kk < 32; kk++) {
                    float2 av = *(float2*)&gA[kk * 18 + ty * 2];
                    unsigned long long a0 = pack2(av.x), a1 = pack2(av.y);
#pragma unroll
                    for (int g = 0; g < 3; g++) {
                        unsigned long long bv = *(unsigned long long*)&gB[(g * 32 + kk) * 68 + tx * 2];
                        fma2(acc[g][0], a0, bv);
                        fma2(acc[g][1], a1, bv);
                    }
                }
                __syncthreads();
            }
            int j = j0 + tx * 2;
            float2 br = *(const float2*)&b_hh[j];
            float2 bz = *(const float2*)&b_hh[H_ + j];
            float2 bn = *(const float2*)&b_hh[2 * H_ + j];
#pragma unroll
            for (int mi = 0; mi < 2; mi++) {
                int b = b0 + ty * 2 + mi;
                int tok = tokens[s * B_ + b];
                const float* gi = (tok == 0) ? b_ih : (g_EMB_GI + (size_t)tok * H3);
                float2 gr = *(const float2*)&gi[j];
                float2 gz = *(const float2*)&gi[H_ + j];
                float2 gn = *(const float2*)&gi[2 * H_ + j];
                float2 hp = __ldcg((const float2*)&hin[b * H_ + j]);
                float2 R = unpack2(acc[0][mi]);
                float2 Z = unpack2(acc[1][mi]);
                float2 N = unpack2(acc[2][mi]);
                float2 o;
                {   float rr = sigmoidf_(gr.x + R.x + br.x);
                    float zz = sigmoidf_(gz.x + Z.x + bz.x);
                    float nn = tanhf(gn.x + rr * (N.x + bn.x));
                    o.x = (1.f - zz) * nn + zz * hp.x; }
                {   float rr = sigmoidf_(gr.y + R.y + br.y);
                    float zz = sigmoidf_(gz.y + Z.y + bz.y);
                    float nn = tanhf(gn.y + rr * (N.y + bn.y));
                    o.y = (1.f - zz) * nn + zz * hp.y; }
                *(float2*)&hout[b * H_ + j] = o;
                *(float2*)&outputs[((size_t)s * B_ + b) * H_ + j] = o;
            }
        } else {
            int b0 = amt * 8, c0 = ajt * 64;
            unsigned long long acc = 0ull;
            float asum = 0.f;
            bool act = (ajt == 0) && (tid < 48);
            int abl = tid / 6, ao = tid % 6;
            for (int k0 = 0; k0 < H_; k0 += 32) {
                {   int m = tid >> 5, kk = tid & 31;
                    aA[kk * 10 + m] = __ldcg(&hin[(b0 + m) * H_ + k0 + kk]); }
                {   int rI = tid >> 3, c = (tid & 7) * 8;
                    const float* src = &g_WstkT[(size_t)(k0 + rI) * (NSTACK * ELEM) + c0 + c];
                    *(float4*)&aB[rI * 68 + c]     = *(const float4*)(src);
                    *(float4*)&aB[rI * 68 + c + 4] = *(const float4*)(src + 4);
                }
                __syncthreads();
#pragma unroll
                for (int kk = 0; kk < 32; kk++) {
                    unsigned long long ap = pack2(aA[kk * 10 + ty]);
                    unsigned long long bv = *(unsigned long long*)&aB[kk * 68 + tx * 2];
                    fma2(acc, ap, bv);
                }
                if (act) {
#pragma unroll 8
                    for (int kk = 0; kk < 32; kk++)
                        asum = fmaf(aA[kk * 10 + abl], W_act[ao * H_ + k0 + kk], asum);
                }
                __syncthreads();
            }
            {   int b = b0 + ty;
                int c = c0 + tx * 2;
                float2 p = unpack2(acc);
                float2 o;
                o.x = tanhf(p.x + b_stk[c]);
                o.y = tanhf(p.y + b_stk[c + 1]);
                *(float2*)&g_PV[s & 1][b * (NSTACK * ELEM) + c] = o; }
            if (ajt == 0) {
                if (tid < 48) lg[tid] = asum + b_act[ao];
                __syncthreads();
                if (tid < 16) {
                    int bl = tid >> 1, n = tid & 1;
                    float l0 = lg[bl * 6 + n * 3 + 0];
                    float l1 = lg[bl * 6 + n * 3 + 1];
                    float l2 = lg[bl * 6 + n * 3 + 2];
                    float mx = fmaxf(l0, fmaxf(l1, l2));
                    float e0 = expf(l0 - mx), e1 = expf(l1 - mx), e2 = expf(l2 - mx);
                    float inv = 1.f / (e0 + e1 + e2);
                    int sid = (b0 + bl) * 2 + n;
                    g_P[s & 1][sid * 3 + 0] = e0 * inv;
                    g_P[s & 1][sid * 3 + 1] = e1 * inv;
                    g_P[s & 1][sid * 3 + 2] = e2 * inv;
                }
            }
        }

        // ---- grid barrier ----
        __threadfence();
        __syncthreads();
        if (tid == 0) {
            atomicAdd(&g_bar, 1u);
            unsigned int target = (unsigned int)NBLK * (unsigned int)(s + 1);
            while (*((volatile unsigned int*)&g_bar) < target) { }
        }
        __syncthreads();
    }

    // ---- final stack update (step S-1) + write out ----
    {
        int ph = (S_ - 1) & 1;
#pragma unroll
        for (int st = 0; st < 4; st++) {
            int sid = blk * 4 + st;
            int b = sid >> 1, n = sid & 1;
            float pp  = __ldcg(&g_P[ph][sid * 3 + 0]);
            float po  = __ldcg(&g_P[ph][sid * 3 + 1]);
            float pn  = __ldcg(&g_P[ph][sid * 3 + 2]);
            float pvv = __ldcg(&g_PV[ph][b * (NSTACK * ELEM) + n * ELEM + e]);
            float* Sm = stk + st * 4096;
            float* dst = stacks_out + (size_t)sid * 4096;
            float r[18];
#pragma unroll
            for (int i = 0; i < 18; i++) {
                int row = qr - 1 + i;
                r[i] = (row >= 0 && row < SSIZE) ? Sm[row * 64 + e] : 0.f;
            }
#pragma unroll
            for (int i = 0; i < 16; i++) {
                int row = qr + i;
                float v;
                if (row == 0)              v = pp * pvv;
                else if (row == SSIZE - 1) v = emp;
                else v = fmaf(pp, r[i], fmaf(po, r[i + 2], pn * r[i + 1]));
                dst[row * 64 + e] = v;
            }
        }
    }
}

// ---------------- softmax over S + weighted sum -> final_hidden ----------------
__global__ void __launch_bounds__(256) attn_final_k(const float* __restrict__ outputs,
                                                    const int* __restrict__ tokens,
                                                    const float* __restrict__ ba2,
                                                    float* __restrict__ fh) {
    int b = blockIdx.x;
    int tid = threadIdx.x;
    int lane = tid & 31, wid = tid >> 5;
    __shared__ float a_sm[S_];
    __shared__ float rmax[8];
    __shared__ float rsum[8];

    float v = g_spart[0][tid * B_ + b] + g_spart[1][tid * B_ + b] + ba2[0];
    if (tokens[tid * B_ + b] == 0) v = -1e30f;

    float m = v;
#pragma unroll
    for (int off = 16; off > 0; off >>= 1) m = fmaxf(m, __shfl_xor_sync(0xffffffffu, m, off));
    if (lane == 0) rmax[wid] = m;
    __syncthreads();
    float mx = rmax[0];
#pragma unroll
    for (int i = 1; i < 8; i++) mx = fmaxf(mx, rmax[i]);
    float e = expf(v - mx);
    float sum = e;
#pragma unroll
    for (int off = 16; off > 0; off >>= 1) sum += __shfl_xor_sync(0xffffffffu, sum, off);
    if (lane == 0) rsum[wid] = sum;
    __syncthreads();
    float tot = rsum[0];
#pragma unroll
    for (int i = 1; i < 8; i++) tot += rsum[i];
    a_sm[tid] = e / tot;
    __syncthreads();

    float acc = 0.f;
    for (int s2 = 0; s2 < S_; s2++)
        acc += a_sm[s2] * outputs[((size_t)s2 * B_ + b) * H_ + tid];
    fh[b * H_ + tid] = acc;
}

// ---------------- launch ----------------
extern "C" void kernel_launch(void* const* d_in, const int* in_sizes, int n_in,
                              void* d_out, int out_size) {
    const int*   tokens     = (const int*)d_in[0];
    const float* emb        = (const float*)d_in[1];
    const float* W_ih       = (const float*)d_in[2];
    const float* W_hh       = (const float*)d_in[3];
    const float* b_ih       = (const float*)d_in[4];
    const float* b_hh       = (const float*)d_in[5];
    const float* W_act      = (const float*)d_in[6];
    const float* b_act      = (const float*)d_in[7];
    const float* W_stk      = (const float*)d_in[8];
    const float* b_stk      = (const float*)d_in[9];
    const float* empty_elem = (const float*)d_in[10];
    // d_in[11] = W_up, d_in[12] = W_down : shift matrices, hardcoded
    const float* Wa1        = (const float*)d_in[13];
    const float* ba1        = (const float*)d_in[14];
    const float* Wa2        = (const float*)d_in[15];
    const float* ba2        = (const float*)d_in[16];

    float* out     = (float*)d_out;
    float* outputs = out;
    float* fh      = out + (size_t)S_ * B_ * H_;
    float* stacks  = fh + (size_t)B_ * H_;

    float *pWihT, *pWa1T, *pEMB;
    cudaGetSymbolAddress((void**)&pWihT, g_WihT);
    cudaGetSymbolAddress((void**)&pWa1T, g_Wa1T);
    cudaGetSymbolAddress((void**)&pEMB,  g_EMB_GI);

    static int smem_set = 0;
    if (!smem_set) {
        cudaFuncSetAttribute(persist_k, cudaFuncAttributeMaxDynamicSharedMemorySize, SMEM_DYN);
        smem_set = 1;
    }

    // launches 0-3: prep
    prep_a<<<(H3 * H_ + 255) / 256, 256>>>(W_ih);
    prep_b<<<(H3 * H_ + 255) / 256, 256>>>(W_hh);
    prep_c<<<(H_ * H_ + 255) / 256, 256>>>(W_stk, Wa1);
    prep_d<<<(B_ * H_ + 255) / 256, 256>>>();

    // launch 4: EMB_GI = emb @ W_ih^T + b_ih  (32000 x 768)
    {
        dim3 grid(H3 / 128, VOCAB_ / 128);
        sgemm128_k<false><<<grid, 256>>>(emb, pWihT, b_ih, pEMB, nullptr, VOCAB_, H3, H_);
    }

    // launch 5: the whole recurrence in ONE persistent kernel
    persist_k<<<NBLK, 256, SMEM_DYN>>>(tokens, b_ih, b_hh, W_act, b_act, b_stk,
                                       empty_elem, outputs, stacks);

    // launch 6: attention partials (fused tanh(outputs@Wa1^T+ba1)@Wa2^T)
    {
        dim3 grid(H_ / 128, (S_ * B_) / 128);
        sgemm128_k<true><<<grid, 256>>>(outputs, pWa1T, ba1, nullptr, Wa2, S_ * B_, H_, H_);
    }
    // launch 7: softmax + weighted sum
    attn_final_k<<<B_, 256>>>(outputs, tokens, ba2, fh);
}

// round 10
// speedup vs baseline: 1.1379x; 1.0871x over previous
#include <cuda_runtime.h>
#include <math.h>

#define S_ 256
#define B_ 512
#define H_ 256
#define H3 768
#define VOCAB_ 32000
#define NSTACK 2
#define SSIZE 64
#define ELEM 64
#define NBLK 256

// A-tile row stride in floats: 260*4 = 1040 bytes, multiple of 16 (float4-safe)
#define APAD 260

// ---------------- device scratch (static, no allocation) ----------------
__device__ float g_EMB_GI[VOCAB_ * H3];       // emb @ W_ih^T + b_ih
__device__ float g_WihT[H_ * H3];             // [k][n]
__device__ float g_WhhT[H_ * H3];             // [k][n]
__device__ float g_WstkT[H_ * 128];           // [k][c]
__device__ float g_Wa1T[H_ * H_];
__device__ float g_h[2][B_ * H_];
__device__ float g_PV[2][B_ * 128];
__device__ float g_P[2][B_ * 2 * 3];
__device__ float g_spart[2][S_ * B_];
__device__ unsigned int g_bar;

__device__ __forceinline__ float sigmoidf_(float x) { return 1.f / (1.f + expf(-x)); }

// ---------------- cp.async helpers ----------------
__device__ __forceinline__ void cp16(float* dst_smem, const float* src) {
    unsigned d = (unsigned)__cvta_generic_to_shared(dst_smem);
    asm volatile("cp.async.cg.shared.global [%0], [%1], 16;" :: "r"(d), "l"(src));
}
__device__ __forceinline__ void cp_commit() { asm volatile("cp.async.commit_group;"); }
template <int N>
__device__ __forceinline__ void cp_wait() { asm volatile("cp.async.wait_group %0;" :: "n"(N)); }

// ---------------- prep kernels ----------------
__global__ void prep_a(const float* __restrict__ W_ih) {
    int idx = blockIdx.x * 256 + threadIdx.x;
    if (idx < H3 * H_) { int r = idx % H3, c = idx / H3; g_WihT[idx] = W_ih[r * H_ + c]; }
}
__global__ void prep_b(const float* __restrict__ W_hh) {
    int idx = blockIdx.x * 256 + threadIdx.x;
    if (idx < H3 * H_) { int r = idx % H3, c = idx / H3; g_WhhT[idx] = W_hh[r * H_ + c]; }
}
__global__ void prep_c(const float* __restrict__ W_stk, const float* __restrict__ Wa1) {
    int idx = blockIdx.x * 256 + threadIdx.x;
    if (idx < 128 * H_) { int r = idx % 128, c = idx / 128; g_WstkT[idx] = W_stk[r * H_ + c]; }
    if (idx < H_ * H_) { int r = idx % H_, c = idx / H_; g_Wa1T[idx] = Wa1[r * H_ + c]; }
}
__global__ void prep_d() {
    int idx = blockIdx.x * 256 + threadIdx.x;
    if (idx < B_ * H_) g_h[0][idx] = 0.f;
    if (idx == 0) g_bar = 0u;
}

// ---------------- 128x128x16 SGEMM (plain FFMA) ----------------
// SCORE=false: C = A@B + bias
// SCORE=true : g_spart[blockIdx.x][m] = sum_n tanh(A@B + bias)[m][n] * Wa2[n]
template <bool SCORE>
__global__ void __launch_bounds__(256) sgemm128_k(
    const float* __restrict__ A, const float* __restrict__ Bm,
    const float* __restrict__ bias, float* __restrict__ C,
    const float* __restrict__ Wa2,
    int M, int N, int K)
{
    __shared__ __align__(16) float As[16][128];   // [k][m]
    __shared__ __align__(16) float Bs[16][128];   // [k][n]
    int tid = threadIdx.x;
    int m0 = blockIdx.y * 128, n0 = blockIdx.x * 128;
    int tx = tid & 15, ty = tid >> 4;
    float acc[2][2][4][4] = {};

    for (int k0 = 0; k0 < K; k0 += 16) {
#pragma unroll
        for (int i = 0; i < 2; i++) {
            int f = tid * 2 + i;
            int arow = f >> 2, aq = (f & 3) * 4;
            float4 v = *(const float4*)&A[(size_t)(m0 + arow) * K + k0 + aq];
            As[aq + 0][arow] = v.x; As[aq + 1][arow] = v.y;
            As[aq + 2][arow] = v.z; As[aq + 3][arow] = v.w;
            int brow = f >> 5, bc = (f & 31) * 4;
            *(float4*)&Bs[brow][bc] = *(const float4*)&Bm[(size_t)(k0 + brow) * N + n0 + bc];
        }
        __syncthreads();
#pragma unroll
        for (int kk = 0; kk < 16; kk++) {
            float a[2][4], b[2][4];
            *(float4*)a[0] = *(float4*)&As[kk][ty * 4];
            *(float4*)a[1] = *(float4*)&As[kk][ty * 4 + 64];
            *(float4*)b[0] = *(float4*)&Bs[kk][tx * 4];
            *(float4*)b[1] = *(float4*)&Bs[kk][tx * 4 + 64];
#pragma unroll
            for (int ic = 0; ic < 2; ic++)
#pragma unroll
                for (int jc = 0; jc < 2; jc++)
#pragma unroll
                    for (int i = 0; i < 4; i++)
#pragma unroll
                        for (int j = 0; j < 4; j++)
                            acc[ic][jc][i][j] = fmaf(a[ic][i], b[jc][j], acc[ic][jc][i][j]);
        }
        __syncthreads();
    }

    if (!SCORE) {
#pragma unroll
        for (int ic = 0; ic < 2; ic++)
#pragma unroll
            for (int i = 0; i < 4; i++) {
                int m = m0 + ic * 64 + ty * 4 + i;
#pragma unroll
                for (int jc = 0; jc < 2; jc++) {
                    int n = n0 + jc * 64 + tx * 4;
                    float4 o;
                    o.x = acc[ic][jc][i][0] + bias[n + 0];
                    o.y = acc[ic][jc][i][1] + bias[n + 1];
                    o.z = acc[ic][jc][i][2] + bias[n + 2];
                    o.w = acc[ic][jc][i][3] + bias[n + 3];
                    *(float4*)&C[(size_t)m * N + n] = o;
                }
            }
    } else {
        float4 bb[2], ww[2];
#pragma unroll
        for (int jc = 0; jc < 2; jc++) {
            int n = n0 + jc * 64 + tx * 4;
            bb[jc] = *(const float4*)&bias[n];
            ww[jc] = *(const float4*)&Wa2[n];
        }
#pragma unroll
        for (int ic = 0; ic < 2; ic++)
#pragma unroll
            for (int i = 0; i < 4; i++) {
                float p = 0.f;
#pragma unroll
                for (int jc = 0; jc < 2; jc++) {
                    p += tanhf(acc[ic][jc][i][0] + bb[jc].x) * ww[jc].x;
                    p += tanhf(acc[ic][jc][i][1] + bb[jc].y) * ww[jc].y;
                    p += tanhf(acc[ic][jc][i][2] + bb[jc].z) * ww[jc].z;
                    p += tanhf(acc[ic][jc][i][3] + bb[jc].w) * ww[jc].w;
                }
#pragma unroll
                for (int off = 8; off > 0; off >>= 1)
                    p += __shfl_xor_sync(0xffffffffu, p, off);
                if (tx == 0) {
                    int m = m0 + ic * 64 + ty * 4 + i;
                    g_spart[blockIdx.x][m] = p;
                }
            }
    }
}

// ---------------- persistent recurrence kernel ----------------
// 256 blocks x 256 threads, 2 blocks/SM, grid barrier per step.
// blocks [0,128):   GRU tile 16 batches x 64 j x 3 gates (plain FFMA, cp.async B)
// blocks [128,256): AUX tile 4 batches x 128 pv-cols + ACT probs
// every block owns 4 SMEM-resident stacks; stack update deferred one step.
#define SMEM_FLOATS (16384 + 16 * APAD + 6272)
#define SMEM_DYN (SMEM_FLOATS * 4)

__global__ void __launch_bounds__(256, 2) persist_k(
    const int* __restrict__ tokens,
    const float* __restrict__ b_ih,
    const float* __restrict__ b_hh,
    const float* __restrict__ W_act,
    const float* __restrict__ b_act,
    const float* __restrict__ b_stk,
    const float* __restrict__ empty_elem,
    float* __restrict__ outputs,
    float* __restrict__ stacks_out)
{
    extern __shared__ __align__(16) float smem[];
    float* stk = smem;                           // 16384
    float* A   = smem + 16384;                   // GRU: [16][APAD]
    float* B0  = smem + 16384 + 16 * APAD;       // GRU: 2 bufs of [16][196]
    float* Aa  = smem + 16384;                   // AUX: [4][APAD]
    float* Bs0 = smem + 16384 + 4 * APAD;        // AUX: 2 bufs of [16][132]
    float* lg  = smem + 16384 + 4 * APAD + 4224; // AUX: 24 logits

    int tid = threadIdx.x, blk = blockIdx.x;
    int e = tid & 63, qr = (tid >> 6) * 16;
    float emp = empty_elem[e];

    for (int i = tid; i < 16384; i += 256) stk[i] = empty_elem[i & 63];

    const bool isGRU = blk < 128;
    int b0 = (blk >> 2) * 16, j0 = (blk & 3) * 64;   // GRU mapping
    int ty = tid >> 4, tx = tid & 15;
    int ab0 = (blk - 128) * 4;                        // AUX mapping
    int aty = tid >> 6, atx = tid & 63;

    for (int s = 0; s < S_; s++) {
        // ---- stack update for step s-1 (SMEM-resident, deferred) ----
        if (s > 0) {
            int ph = (s - 1) & 1;
#pragma unroll
            for (int st = 0; st < 4; st++) {
                int sid = blk * 4 + st;
                int b = sid >> 1, n = sid & 1;
                float pp  = __ldcg(&g_P[ph][sid * 3 + 0]);
                float po  = __ldcg(&g_P[ph][sid * 3 + 1]);
                float pn  = __ldcg(&g_P[ph][sid * 3 + 2]);
                float pvv = __ldcg(&g_PV[ph][b * 128 + n * 64 + e]);
                float* Sm = stk + st * 4096;
                float r[18];
#pragma unroll
                for (int i = 0; i < 18; i++) {
                    int row = qr - 1 + i;
                    r[i] = (row >= 0 && row < SSIZE) ? Sm[row * 64 + e] : 0.f;
                }
                __syncthreads();
#pragma unroll
                for (int i = 0; i < 16; i++) {
                    int row = qr + i; float v;
                    if (row == 0)              v = pp * pvv;
                    else if (row == SSIZE - 1) v = emp;
                    else v = fmaf(pp, r[i], fmaf(po, r[i + 2], pn * r[i + 1]));
                    Sm[row * 64 + e] = v;
                }
                __syncthreads();
            }
        }

        const float* hin = g_h[s & 1];
        if (isGRU) {
            float* hout = g_h[(s + 1) & 1];
            // A tile: 16 rows x 256 k, once per step, coalesced
            {
                int m = tid >> 4, kq = (tid & 15) * 16;
                const float* src = hin + (b0 + m) * H_ + kq;
                float4 v0 = __ldcg((const float4*)(src + 0));
                float4 v1 = __ldcg((const float4*)(src + 4));
                float4 v2 = __ldcg((const float4*)(src + 8));
                float4 v3 = __ldcg((const float4*)(src + 12));
                float* d = A + m * APAD + kq;
                *(float4*)(d + 0) = v0; *(float4*)(d + 4)  = v1;
                *(float4*)(d + 8) = v2; *(float4*)(d + 12) = v3;
            }
            // epilogue prefetch (hidden under GEMM)
            int b = b0 + ty, j = j0 + tx * 4;
            int tok = __ldg(&tokens[s * B_ + b]);
            const float* gi = (tok == 0) ? b_ih : (g_EMB_GI + (size_t)tok * H3);
            float4 gr = *(const float4*)(gi + j);
            float4 gz = *(const float4*)(gi + H_ + j);
            float4 gn = *(const float4*)(gi + 2 * H_ + j);
            float4 hp = __ldcg((const float4*)(hin + b * H_ + j));
            // prefetch B chunk 0
#pragma unroll
            for (int i = 0; i < 3; i++) {
                int idx = tid + i * 256;
                int kk = idx / 48, r = idx % 48, g = r >> 4, l = r & 15;
                cp16(B0 + kk * 196 + g * 64 + l * 4,
                     g_WhhT + (size_t)kk * H3 + g * H_ + j0 + l * 4);
            }
            cp_commit();

            float accr[4] = {}, accz[4] = {}, accn[4] = {};
            __syncthreads();   // A ready
            for (int c = 0; c < 16; c++) {
                float* Bc = B0 + (c & 1) * 3136;
                if (c + 1 < 16) {
                    float* Bn = B0 + ((c + 1) & 1) * 3136;
                    int kb = (c + 1) * 16;
#pragma unroll
                    for (int i = 0; i < 3; i++) {
                        int idx = tid + i * 256;
                        int kk = idx / 48, r = idx % 48, g = r >> 4, l = r & 15;
                        cp16(Bn + kk * 196 + g * 64 + l * 4,
                             g_WhhT + (size_t)(kb + kk) * H3 + g * H_ + j0 + l * 4);
                    }
                    cp_commit();
                    cp_wait<1>();
                } else {
                    cp_wait<0>();
                }
                __syncthreads();
                const float* Arow = A + ty * APAD + c * 16;
#pragma unroll
                for (int kk = 0; kk < 16; kk++) {
                    float a = Arow[kk];
                    float4 br = *(float4*)(Bc + kk * 196 + tx * 4);
                    float4 bz = *(float4*)(Bc + kk * 196 + 64 + tx * 4);
                    float4 bn = *(float4*)(Bc + kk * 196 + 128 + tx * 4);
                    accr[0] = fmaf(a, br.x, accr[0]); accr[1] = fmaf(a, br.y, accr[1]);
                    accr[2] = fmaf(a, br.z, accr[2]); accr[3] = fmaf(a, br.w, accr[3]);
                    accz[0] = fmaf(a, bz.x, accz[0]); accz[1] = fmaf(a, bz.y, accz[1]);
                    accz[2] = fmaf(a, bz.z, accz[2]); accz[3] = fmaf(a, bz.w, accz[3]);
                    accn[0] = fmaf(a, bn.x, accn[0]); accn[1] = fmaf(a, bn.y, accn[1]);
                    accn[2] = fmaf(a, bn.z, accn[2]); accn[3] = fmaf(a, bn.w, accn[3]);
                }
                __syncthreads();
            }
            float4 bhr = __ldg((const float4*)(b_hh + j));
            float4 bhz = __ldg((const float4*)(b_hh + H_ + j));
            float4 bhn = __ldg((const float4*)(b_hh + 2 * H_ + j));
            float4 o;
            { float rr = sigmoidf_(gr.x + accr[0] + bhr.x);
              float zz = sigmoidf_(gz.x + accz[0] + bhz.x);
              float nn = tanhf(gn.x + rr * (accn[0] + bhn.x));
              o.x = (1.f - zz) * nn + zz * hp.x; }
            { float rr = sigmoidf_(gr.y + accr[1] + bhr.y);
              float zz = sigmoidf_(gz.y + accz[1] + bhz.y);
              float nn = tanhf(gn.y + rr * (accn[1] + bhn.y));
              o.y = (1.f - zz) * nn + zz * hp.y; }
            { float rr = sigmoidf_(gr.z + accr[2] + bhr.z);
              float zz = sigmoidf_(gz.z + accz[2] + bhz.z);
              float nn = tanhf(gn.z + rr * (accn[2] + bhn.z));
              o.z = (1.f - zz) * nn + zz * hp.z; }
            { float rr = sigmoidf_(gr.w + accr[3] + bhr.w);
              float zz = sigmoidf_(gz.w + accz[3] + bhz.w);
              float nn = tanhf(gn.w + rr * (accn[3] + bhn.w));
              o.w = (1.f - zz) * nn + zz * hp.w; }
            *(float4*)(hout + b * H_ + j) = o;
            *(float4*)(outputs + ((size_t)s * B_ + b) * H_ + j) = o;
        } else {
            // ---- AUX: PV (4b x 128c) + ACT probs ----
            {
                int m = tid >> 6, kq = (tid & 63) * 4;
                float4 v = __ldcg((const float4*)(hin + (ab0 + m) * H_ + kq));
                *(float4*)(Aa + m * APAD + kq) = v;
            }
#pragma unroll
            for (int i = 0; i < 2; i++) {
                int idx = tid + i * 256;
                int kk = idx >> 5, l = idx & 31;
                cp16(Bs0 + kk * 132 + l * 4, g_WstkT + (size_t)kk * 128 + l * 4);
            }
            cp_commit();
            float acc0 = 0.f, acc1 = 0.f;
            __syncthreads();
            for (int c = 0; c < 16; c++) {
                float* Bc = Bs0 + (c & 1) * 2112;
                if (c + 1 < 16) {
                    float* Bn = Bs0 + ((c + 1) & 1) * 2112;
                    int kb = (c + 1) * 16;
#pragma unroll
                    for (int i = 0; i < 2; i++) {
                        int idx = tid + i * 256;
                        int kk = idx >> 5, l = idx & 31;
                        cp16(Bn + kk * 132 + l * 4, g_WstkT + (size_t)(kb + kk) * 128 + l * 4);
                    }
                    cp_commit();
                    cp_wait<1>();
                } else {
                    cp_wait<0>();
                }
                __syncthreads();
                const float* Arow = Aa + aty * APAD + c * 16;
#pragma unroll
                for (int kk = 0; kk < 16; kk++) {
                    float a = Arow[kk];
                    float2 bv = *(float2*)(Bc + kk * 132 + atx * 2);
                    acc0 = fmaf(a, bv.x, acc0);
                    acc1 = fmaf(a, bv.y, acc1);
                }
                __syncthreads();
            }
            {
                int b = ab0 + aty, cc = atx * 2;
                float2 o;
                o.x = tanhf(acc0 + __ldg(&b_stk[cc]));
                o.y = tanhf(acc1 + __ldg(&b_stk[cc + 1]));
                *(float2*)&g_PV[s & 1][b * 128 + cc] = o;
            }
            // ACT logits: 4 batches x 2 stacks x 3 actions
            if (tid < 24) {
                int pair = tid / 3, o = tid - pair * 3;
                int bl = pair >> 1, n = pair & 1;
                const float* wr = W_act + (n * 3 + o) * H_;
                const float* ar = Aa + bl * APAD;
                float sum = __ldg(&b_act[n * 3 + o]);
#pragma unroll 8
                for (int k = 0; k < H_; k++) sum = fmaf(ar[k], __ldg(&wr[k]), sum);
                lg[tid] = sum;
            }
            __syncthreads();
            if (tid < 8) {
                float l0 = lg[tid * 3 + 0], l1 = lg[tid * 3 + 1], l2 = lg[tid * 3 + 2];
                float mx = fmaxf(l0, fmaxf(l1, l2));
                float e0 = expf(l0 - mx), e1 = expf(l1 - mx), e2 = expf(l2 - mx);
                float inv = 1.f / (e0 + e1 + e2);
                int bl = tid >> 1, n = tid & 1;
                int sid = (ab0 + bl) * 2 + n;
                g_P[s & 1][sid * 3 + 0] = e0 * inv;
                g_P[s & 1][sid * 3 + 1] = e1 * inv;
                g_P[s & 1][sid * 3 + 2] = e2 * inv;
            }
        }

        // ---- grid barrier ----
        __threadfence();
        __syncthreads();
        if (tid == 0) {
            atomicAdd(&g_bar, 1u);
            unsigned int target = (unsigned int)NBLK * (unsigned int)(s + 1);
            while (*((volatile unsigned int*)&g_bar) < target) { }
        }
        __syncthreads();
    }

    // ---- final stack update (step S-1) + write out ----
    {
        int ph = (S_ - 1) & 1;
#pragma unroll
        for (int st = 0; st < 4; st++) {
            int sid = blk * 4 + st;
            int b = sid >> 1, n = sid & 1;
            float pp  = __ldcg(&g_P[ph][sid * 3 + 0]);
            float po  = __ldcg(&g_P[ph][sid * 3 + 1]);
            float pn  = __ldcg(&g_P[ph][sid * 3 + 2]);
            float pvv = __ldcg(&g_PV[ph][b * 128 + n * 64 + e]);
            float* Sm = stk + st * 4096;
            float* dst = stacks_out + (size_t)sid * 4096;
            float r[18];
#pragma unroll
            for (int i = 0; i < 18; i++) {
                int row = qr - 1 + i;
                r[i] = (row >= 0 && row < SSIZE) ? Sm[row * 64 + e] : 0.f;
            }
#pragma unroll
            for (int i = 0; i < 16; i++) {
                int row = qr + i; float v;
                if (row == 0)              v = pp * pvv;
                else if (row == SSIZE - 1) v = emp;
                else v = fmaf(pp, r[i], fmaf(po, r[i + 2], pn * r[i + 1]));
                dst[row * 64 + e] = v;
            }
        }
    }
}

// ---------------- softmax over S + weighted sum -> final_hidden ----------------
__global__ void __launch_bounds__(256) attn_final_k(const float* __restrict__ outputs,
                                                    const int* __restrict__ tokens,
                                                    const float* __restrict__ ba2,
                                                    float* __restrict__ fh) {
    int b = blockIdx.x;
    int tid = threadIdx.x;
    int lane = tid & 31, wid = tid >> 5;
    __shared__ float a_sm[S_];
    __shared__ float rmax[8];
    __shared__ float rsum[8];

    float v = g_spart[0][tid * B_ + b] + g_spart[1][tid * B_ + b] + ba2[0];
    if (tokens[tid * B_ + b] == 0) v = -1e30f;

    float m = v;
#pragma unroll
    for (int off = 16; off > 0; off >>= 1) m = fmaxf(m, __shfl_xor_sync(0xffffffffu, m, off));
    if (lane == 0) rmax[wid] = m;
    __syncthreads();
    float mx = rmax[0];
#pragma unroll
    for (int i = 1; i < 8; i++) mx = fmaxf(mx, rmax[i]);
    float e = expf(v - mx);
    float sum = e;
#pragma unroll
    for (int off = 16; off > 0; off >>= 1) sum += __shfl_xor_sync(0xffffffffu, sum, off);
    if (lane == 0) rsum[wid] = sum;
    __syncthreads();
    float tot = rsum[0];
#pragma unroll
    for (int i = 1; i < 8; i++) tot += rsum[i];
    a_sm[tid] = e / tot;
    __syncthreads();

    float acc = 0.f;
    for (int s2 = 0; s2 < S_; s2++)
        acc += a_sm[s2] * outputs[((size_t)s2 * B_ + b) * H_ + tid];
    fh[b * H_ + tid] = acc;
}

// ---------------- launch ----------------
extern "C" void kernel_launch(void* const* d_in, const int* in_sizes, int n_in,
                              void* d_out, int out_size) {
    const int*   tokens     = (const int*)d_in[0];
    const float* emb        = (const float*)d_in[1];
    const float* W_ih       = (const float*)d_in[2];
    const float* W_hh       = (const float*)d_in[3];
    const float* b_ih       = (const float*)d_in[4];
    const float* b_hh       = (const float*)d_in[5];
    const float* W_act      = (const float*)d_in[6];
    const float* b_act      = (const float*)d_in[7];
    const float* W_stk      = (const float*)d_in[8];
    const float* b_stk      = (const float*)d_in[9];
    const float* empty_elem = (const float*)d_in[10];
    // d_in[11] = W_up, d_in[12] = W_down : shift matrices, hardcoded
    const float* Wa1        = (const float*)d_in[13];
    const float* ba1        = (const float*)d_in[14];
    const float* Wa2        = (const float*)d_in[15];
    const float* ba2        = (const float*)d_in[16];

    float* out     = (float*)d_out;
    float* outputs = out;
    float* fh      = out + (size_t)S_ * B_ * H_;
    float* stacks  = fh + (size_t)B_ * H_;

    float *pWihT, *pWa1T, *pEMB;
    cudaGetSymbolAddress((void**)&pWihT, g_WihT);
    cudaGetSymbolAddress((void**)&pWa1T, g_Wa1T);
    cudaGetSymbolAddress((void**)&pEMB,  g_EMB_GI);

    static int smem_set = 0;
    if (!smem_set) {
        cudaFuncSetAttribute(persist_k, cudaFuncAttributeMaxDynamicSharedMemorySize, SMEM_DYN);
        smem_set = 1;
    }

    // prep — NOTE: prep_c grid must cover H_*H_ (Wa1T), not just 128*H_
    prep_a<<<(H3 * H_ + 255) / 256, 256>>>(W_ih);
    prep_b<<<(H3 * H_ + 255) / 256, 256>>>(W_hh);
    prep_c<<<(H_ * H_ + 255) / 256, 256>>>(W_stk, Wa1);
    prep_d<<<(B_ * H_ + 255) / 256, 256>>>();

    // EMB_GI = emb @ W_ih^T + b_ih  (32000 x 768)
    {
        dim3 grid(H3 / 128, VOCAB_ / 128);
        sgemm128_k<false><<<grid, 256>>>(emb, pWihT, b_ih, pEMB, nullptr, VOCAB_, H3, H_);
    }

    // the whole recurrence in ONE persistent kernel
    persist_k<<<NBLK, 256, SMEM_DYN>>>(tokens, b_ih, b_hh, W_act, b_act, b_stk,
                                       empty_elem, outputs, stacks);

    // attention partials (fused tanh(outputs@Wa1^T+ba1)@Wa2^T)
    {
        dim3 grid(H_ / 128, (S_ * B_) / 128);
        sgemm128_k<true><<<grid, 256>>>(outputs, pWa1T, ba1, nullptr, Wa2, S_ * B_, H_, H_);
    }
    attn_final_k<<<B_, 256>>>(outputs, tokens, ba2, fh);
}

// round 11
// speedup vs baseline: 1.2187x; 1.0710x over previous
#include <cuda_runtime.h>
#include <math.h>

#define S_ 256
#define B_ 512
#define H_ 256
#define H3 768
#define VOCAB_ 32000
#define NSTACK 2
#define SSIZE 64
#define ELEM 64
#define NBLK 256
#define APAD 260   // A row stride (floats), 1040B = 16B multiple

// ---------------- device scratch ----------------
__device__ float g_EMB_GI[VOCAB_ * H3];
__device__ float g_WihT[H_ * H3];
__device__ float g_WhhT[H_ * H3];
__device__ float g_WstkT[H_ * 128];
__device__ float g_Wa1T[H_ * H_];
__device__ float g_h[2][B_ * H_];
__device__ float g_PV[4][B_ * 128];     // 4-deep: stack update reads (s-1)&3 post-arrive
__device__ float g_P[4][B_ * 2 * 3];
__device__ float g_spart[2][S_ * B_];
__device__ unsigned int g_bar;

__device__ __forceinline__ float sigmoidf_(float x) { return 1.f / (1.f + expf(-x)); }

// ---------------- cp.async helpers ----------------
__device__ __forceinline__ void cp16(float* dst_smem, const float* src) {
    unsigned d = (unsigned)__cvta_generic_to_shared(dst_smem);
    asm volatile("cp.async.cg.shared.global [%0], [%1], 16;" :: "r"(d), "l"(src));
}
__device__ __forceinline__ void cp_commit() { asm volatile("cp.async.commit_group;"); }
template <int N>
__device__ __forceinline__ void cp_wait() { asm volatile("cp.async.wait_group %0;" :: "n"(N)); }

// ---------------- prep kernels (2 so persist = my launch index 3 = ncu slot 5) ----------------
__global__ void prep1(const float* __restrict__ W_ih, const float* __restrict__ W_hh) {
    int idx = blockIdx.x * 256 + threadIdx.x;
    if (idx < H3 * H_) {
        int r = idx % H3, c = idx / H3;
        g_WihT[idx] = W_ih[r * H_ + c];
        g_WhhT[idx] = W_hh[r * H_ + c];
    }
}
__global__ void prep2(const float* __restrict__ W_stk, const float* __restrict__ Wa1) {
    int idx = blockIdx.x * 256 + threadIdx.x;
    if (idx < 128 * H_) { int r = idx % 128, c = idx / 128; g_WstkT[idx] = W_stk[r * H_ + c]; }
    if (idx < H_ * H_) { int r = idx % H_, c = idx / H_; g_Wa1T[idx] = Wa1[r * H_ + c]; }
    if (idx < B_ * H_) g_h[0][idx] = 0.f;
    if (idx == 0) g_bar = 0u;
}

// ---------------- 128x128x16 SGEMM (plain FFMA) ----------------
template <bool SCORE>
__global__ void __launch_bounds__(256) sgemm128_k(
    const float* __restrict__ A, const float* __restrict__ Bm,
    const float* __restrict__ bias, float* __restrict__ C,
    const float* __restrict__ Wa2,
    int M, int N, int K)
{
    __shared__ __align__(16) float As[16][128];
    __shared__ __align__(16) float Bs[16][128];
    int tid = threadIdx.x;
    int m0 = blockIdx.y * 128, n0 = blockIdx.x * 128;
    int tx = tid & 15, ty = tid >> 4;
    float acc[2][2][4][4] = {};

    for (int k0 = 0; k0 < K; k0 += 16) {
#pragma unroll
        for (int i = 0; i < 2; i++) {
            int f = tid * 2 + i;
            int arow = f >> 2, aq = (f & 3) * 4;
            float4 v = *(const float4*)&A[(size_t)(m0 + arow) * K + k0 + aq];
            As[aq + 0][arow] = v.x; As[aq + 1][arow] = v.y;
            As[aq + 2][arow] = v.z; As[aq + 3][arow] = v.w;
            int brow = f >> 5, bc = (f & 31) * 4;
            *(float4*)&Bs[brow][bc] = *(const float4*)&Bm[(size_t)(k0 + brow) * N + n0 + bc];
        }
        __syncthreads();
#pragma unroll
        for (int kk = 0; kk < 16; kk++) {
            float a[2][4], b[2][4];
            *(float4*)a[0] = *(float4*)&As[kk][ty * 4];
            *(float4*)a[1] = *(float4*)&As[kk][ty * 4 + 64];
            *(float4*)b[0] = *(float4*)&Bs[kk][tx * 4];
            *(float4*)b[1] = *(float4*)&Bs[kk][tx * 4 + 64];
#pragma unroll
            for (int ic = 0; ic < 2; ic++)
#pragma unroll
                for (int jc = 0; jc < 2; jc++)
#pragma unroll
                    for (int i = 0; i < 4; i++)
#pragma unroll
                        for (int j = 0; j < 4; j++)
                            acc[ic][jc][i][j] = fmaf(a[ic][i], b[jc][j], acc[ic][jc][i][j]);
        }
        __syncthreads();
    }

    if (!SCORE) {
#pragma unroll
        for (int ic = 0; ic < 2; ic++)
#pragma unroll
            for (int i = 0; i < 4; i++) {
                int m = m0 + ic * 64 + ty * 4 + i;
#pragma unroll
                for (int jc = 0; jc < 2; jc++) {
                    int n = n0 + jc * 64 + tx * 4;
                    float4 o;
                    o.x = acc[ic][jc][i][0] + bias[n + 0];
                    o.y = acc[ic][jc][i][1] + bias[n + 1];
                    o.z = acc[ic][jc][i][2] + bias[n + 2];
                    o.w = acc[ic][jc][i][3] + bias[n + 3];
                    *(float4*)&C[(size_t)m * N + n] = o;
                }
            }
    } else {
        float4 bb[2], ww[2];
#pragma unroll
        for (int jc = 0; jc < 2; jc++) {
            int n = n0 + jc * 64 + tx * 4;
            bb[jc] = *(const float4*)&bias[n];
            ww[jc] = *(const float4*)&Wa2[n];
        }
#pragma unroll
        for (int ic = 0; ic < 2; ic++)
#pragma unroll
            for (int i = 0; i < 4; i++) {
                float p = 0.f;
#pragma unroll
                for (int jc = 0; jc < 2; jc++) {
                    p += tanhf(acc[ic][jc][i][0] + bb[jc].x) * ww[jc].x;
                    p += tanhf(acc[ic][jc][i][1] + bb[jc].y) * ww[jc].y;
                    p += tanhf(acc[ic][jc][i][2] + bb[jc].z) * ww[jc].z;
                    p += tanhf(acc[ic][jc][i][3] + bb[jc].w) * ww[jc].w;
                }
#pragma unroll
                for (int off = 8; off > 0; off >>= 1)
                    p += __shfl_xor_sync(0xffffffffu, p, off);
                if (tx == 0) {
                    int m = m0 + ic * 64 + ty * 4 + i;
                    g_spart[blockIdx.x][m] = p;
                }
            }
    }
}

// ---------------- persistent recurrence kernel ----------------
// 256 blocks x 256 threads, 2/SM. Per step: compute -> fence/arrive -> stack update
// (hidden in barrier-wait window) -> spin. Stack update is column-owned: zero syncs.
#define SMEM_FLOATS (16384 + 16 * APAD + 6272)
#define SMEM_DYN (SMEM_FLOATS * 4)

__global__ void __launch_bounds__(256, 2) persist_k(
    const int* __restrict__ tokens,
    const float* __restrict__ b_ih,
    const float* __restrict__ b_hh,
    const float* __restrict__ W_act,
    const float* __restrict__ b_act,
    const float* __restrict__ b_stk,
    const float* __restrict__ empty_elem,
    float* __restrict__ outputs,
    float* __restrict__ stacks_out)
{
    extern __shared__ __align__(16) float smem[];
    float* stk = smem;                           // 4 stacks, 16384 floats
    float* A   = smem + 16384;                   // GRU: [16][APAD]
    float* B0  = smem + 16384 + 16 * APAD;       // GRU: 2 x [16][196]
    float* Aa  = smem + 16384;                   // AUX: [4][APAD]
    float* Bs0 = smem + 16384 + 4 * APAD;        // AUX: 2 x [16][132]
    float* lg  = smem + 16384 + 4 * APAD + 4224; // AUX: 24 logits

    int tid = threadIdx.x, blk = blockIdx.x;
    int e = tid & 63, st = tid >> 6;             // stack column ownership
    float emp = empty_elem[e];

    for (int i = tid; i < 16384; i += 256) stk[i] = empty_elem[i & 63];

    const bool isGRU = blk < 128;
    int b0 = (blk >> 2) * 16, j0 = (blk & 3) * 64;   // GRU mapping
    int ty = tid >> 4, tx = tid & 15;
    int ab0 = (blk - 128) * 4;                        // AUX mapping
    int aty = tid >> 6, atx = tid & 63;
    int wwid = tid >> 5, lane = tid & 31;

    for (int s = 0; s < S_; s++) {
        const float* hin = g_h[s & 1];
        if (isGRU) {
            float* hout = g_h[(s + 1) & 1];
            // A tile: 16 rows x 256 k
            {
                int m = tid >> 4, kq = (tid & 15) * 16;
                const float* src = hin + (b0 + m) * H_ + kq;
                float4 v0 = __ldcg((const float4*)(src + 0));
                float4 v1 = __ldcg((const float4*)(src + 4));
                float4 v2 = __ldcg((const float4*)(src + 8));
                float4 v3 = __ldcg((const float4*)(src + 12));
                float* d = A + m * APAD + kq;
                *(float4*)(d + 0) = v0; *(float4*)(d + 4)  = v1;
                *(float4*)(d + 8) = v2; *(float4*)(d + 12) = v3;
            }
            // epilogue operand prefetch (hidden under GEMM)
            int b = b0 + ty, j = j0 + tx * 4;
            int tok = __ldg(&tokens[s * B_ + b]);
            const float* gi = (tok == 0) ? b_ih : (g_EMB_GI + (size_t)tok * H3);
            float4 gr = *(const float4*)(gi + j);
            float4 gz = *(const float4*)(gi + H_ + j);
            float4 gn = *(const float4*)(gi + 2 * H_ + j);
            float4 hp = __ldcg((const float4*)(hin + b * H_ + j));
            // prefetch chunk 0
#pragma unroll
            for (int i = 0; i < 3; i++) {
                int idx = tid + i * 256;
                int kk = idx / 48, r = idx % 48, g = r >> 4, l = r & 15;
                cp16(B0 + kk * 196 + g * 64 + l * 4,
                     g_WhhT + (size_t)kk * H3 + g * H_ + j0 + l * 4);
            }
            cp_commit();

            float accr[4] = {}, accz[4] = {}, accn[4] = {};
            __syncthreads();   // A visible
            for (int c = 0; c < 16; c++) {
                float* Bc = B0 + (c & 1) * 3136;
                if (c + 1 < 16) {
                    // safe: trailing sync of iter c-1 means all warps finished reading buf (c+1)&1
                    float* Bn = B0 + ((c + 1) & 1) * 3136;
                    int kb = (c + 1) * 16;
#pragma unroll
                    for (int i = 0; i < 3; i++) {
                        int idx = tid + i * 256;
                        int kk = idx / 48, r = idx % 48, g = r >> 4, l = r & 15;
                        cp16(Bn + kk * 196 + g * 64 + l * 4,
                             g_WhhT + (size_t)(kb + kk) * H3 + g * H_ + j0 + l * 4);
                    }
                    cp_commit();
                    cp_wait<1>();
                } else {
                    cp_wait<0>();
                }
                __syncthreads();
                // hoist chunk A values to registers (4 x LDS.128)
                float a[16];
                {
                    const float4* Ar = (const float4*)(A + ty * APAD + c * 16);
                    *(float4*)&a[0]  = Ar[0];
                    *(float4*)&a[4]  = Ar[1];
                    *(float4*)&a[8]  = Ar[2];
                    *(float4*)&a[12] = Ar[3];
                }
#pragma unroll
                for (int kk = 0; kk < 16; kk++) {
                    float av = a[kk];
                    float4 br = *(float4*)(Bc + kk * 196 + tx * 4);
                    float4 bz = *(float4*)(Bc + kk * 196 + 64 + tx * 4);
                    float4 bn = *(float4*)(Bc + kk * 196 + 128 + tx * 4);
                    accr[0] = fmaf(av, br.x, accr[0]); accr[1] = fmaf(av, br.y, accr[1]);
                    accr[2] = fmaf(av, br.z, accr[2]); accr[3] = fmaf(av, br.w, accr[3]);
                    accz[0] = fmaf(av, bz.x, accz[0]); accz[1] = fmaf(av, bz.y, accz[1]);
                    accz[2] = fmaf(av, bz.z, accz[2]); accz[3] = fmaf(av, bz.w, accz[3]);
                    accn[0] = fmaf(av, bn.x, accn[0]); accn[1] = fmaf(av, bn.y, accn[1]);
                    accn[2] = fmaf(av, bn.z, accn[2]); accn[3] = fmaf(av, bn.w, accn[3]);
                }
                __syncthreads();
            }
            float4 bhr = __ldg((const float4*)(b_hh + j));
            float4 bhz = __ldg((const float4*)(b_hh + H_ + j));
            float4 bhn = __ldg((const float4*)(b_hh + 2 * H_ + j));
            float4 o;
            { float rr = sigmoidf_(gr.x + accr[0] + bhr.x);
              float zz = sigmoidf_(gz.x + accz[0] + bhz.x);
              float nn = tanhf(gn.x + rr * (accn[0] + bhn.x));
              o.x = (1.f - zz) * nn + zz * hp.x; }
            { float rr = sigmoidf_(gr.y + accr[1] + bhr.y);
              float zz = sigmoidf_(gz.y + accz[1] + bhz.y);
              float nn = tanhf(gn.y + rr * (accn[1] + bhn.y));
              o.y = (1.f - zz) * nn + zz * hp.y; }
            { float rr = sigmoidf_(gr.z + accr[2] + bhr.z);
              float zz = sigmoidf_(gz.z + accz[2] + bhz.z);
              float nn = tanhf(gn.z + rr * (accn[2] + bhn.z));
              o.z = (1.f - zz) * nn + zz * hp.z; }
            { float rr = sigmoidf_(gr.w + accr[3] + bhr.w);
              float zz = sigmoidf_(gz.w + accz[3] + bhz.w);
              float nn = tanhf(gn.w + rr * (accn[3] + bhn.w));
              o.w = (1.f - zz) * nn + zz * hp.w; }
            *(float4*)(hout + b * H_ + j) = o;
            *(float4*)(outputs + ((size_t)s * B_ + b) * H_ + j) = o;
        } else {
            // ---- AUX: PV (4b x 128c) + ACT probs ----
            {
                int m = tid >> 6, kq = (tid & 63) * 4;
                float4 v = __ldcg((const float4*)(hin + (ab0 + m) * H_ + kq));
                *(float4*)(Aa + m * APAD + kq) = v;
            }
#pragma unroll
            for (int i = 0; i < 2; i++) {
                int idx = tid + i * 256;
                int kk = idx >> 5, l = idx & 31;
                cp16(Bs0 + kk * 132 + l * 4, g_WstkT + (size_t)kk * 128 + l * 4);
            }
            cp_commit();
            float acc0 = 0.f, acc1 = 0.f;
            __syncthreads();
            for (int c = 0; c < 16; c++) {
                float* Bc = Bs0 + (c & 1) * 2112;
                if (c + 1 < 16) {
                    float* Bn = Bs0 + ((c + 1) & 1) * 2112;
                    int kb = (c + 1) * 16;
#pragma unroll
                    for (int i = 0; i < 2; i++) {
                        int idx = tid + i * 256;
                        int kk = idx >> 5, l = idx & 31;
                        cp16(Bn + kk * 132 + l * 4, g_WstkT + (size_t)(kb + kk) * 128 + l * 4);
                    }
                    cp_commit();
                    cp_wait<1>();
                } else {
                    cp_wait<0>();
                }
                __syncthreads();
                const float* Arow = Aa + aty * APAD + c * 16;
#pragma unroll
                for (int kk = 0; kk < 16; kk++) {
                    float a = Arow[kk];
                    float2 bv = *(float2*)(Bc + kk * 132 + atx * 2);
                    acc0 = fmaf(a, bv.x, acc0);
                    acc1 = fmaf(a, bv.y, acc1);
                }
                __syncthreads();
            }
            {
                int b = ab0 + aty, cc = atx * 2;
                float2 o;
                o.x = tanhf(acc0 + __ldg(&b_stk[cc]));
                o.y = tanhf(acc1 + __ldg(&b_stk[cc + 1]));
                *(float2*)&g_PV[s & 3][b * 128 + cc] = o;
            }
            // ACT logits: 24 dots, 3 per warp, lane-parallel + shfl reduce
            {
#pragma unroll
                for (int q = 0; q < 3; q++) {
                    int d = wwid * 3 + q;          // 0..23
                    int bl = d / 6, o = d % 6;
                    const float* ar = Aa + bl * APAD;
                    const float* wr = W_act + o * H_;
                    float sum = 0.f;
#pragma unroll
                    for (int k = lane; k < H_; k += 32)
                        sum = fmaf(ar[k], __ldg(&wr[k]), sum);
#pragma unroll
                    for (int off = 16; off > 0; off >>= 1)
                        sum += __shfl_xor_sync(0xffffffffu, sum, off);
                    if (lane == 0) lg[d] = sum + __ldg(&b_act[o]);
                }
            }
            __syncthreads();
            if (tid < 8) {
                float l0 = lg[tid * 3 + 0], l1 = lg[tid * 3 + 1], l2 = lg[tid * 3 + 2];
                float mx = fmaxf(l0, fmaxf(l1, l2));
                float e0 = expf(l0 - mx), e1 = expf(l1 - mx), e2 = expf(l2 - mx);
                float inv = 1.f / (e0 + e1 + e2);
                int bl = tid >> 1, n = tid & 1;
                int sid = (ab0 + bl) * 2 + n;
                g_P[s & 3][sid * 3 + 0] = e0 * inv;
                g_P[s & 3][sid * 3 + 1] = e1 * inv;
                g_P[s & 3][sid * 3 + 2] = e2 * inv;
            }
        }

        // ---- arrive ----
        __threadfence();
        __syncthreads();
        if (tid == 0) atomicAdd(&g_bar, 1u);

        // ---- stack update for step s-1, hidden in barrier-wait window ----
        // column-owned: thread handles stack st, element e, all 64 rows. No syncs.
        if (s > 0) {
            int ph = (s - 1) & 3;
            int sid = blk * 4 + st;
            int bb = sid >> 1, nn = sid & 1;
            float pp  = __ldcg(&g_P[ph][sid * 3 + 0]);
            float po  = __ldcg(&g_P[ph][sid * 3 + 1]);
            float pn  = __ldcg(&g_P[ph][sid * 3 + 2]);
            float pvv = __ldcg(&g_PV[ph][bb * 128 + nn * 64 + e]);
            float* Sm = stk + st * 4096;
            float prev = 0.f, cur = Sm[e];
            float first = pp * pvv;
#pragma unroll 16
            for (int row = 0; row < SSIZE; row++) {
                float nxt = (row < SSIZE - 1) ? Sm[(row + 1) * 64 + e] : 0.f;
                float v;
                if (row == 0)              v = first;
                else if (row == SSIZE - 1) v = emp;
                else v = fmaf(pp, prev, fmaf(po, nxt, pn * cur));
                Sm[row * 64 + e] = v;
                prev = cur; cur = nxt;
            }
        }

        // ---- spin ----
        if (tid == 0) {
            unsigned int target = (unsigned int)NBLK * (unsigned int)(s + 1);
            while (*((volatile unsigned int*)&g_bar) < target) { }
        }
        __syncthreads();
    }

    // ---- final stack update (step S-1) + write out ----
    {
        int ph = (S_ - 1) & 3;
        int sid = blk * 4 + st;
        int bb = sid >> 1, nn = sid & 1;
        float pp  = __ldcg(&g_P[ph][sid * 3 + 0]);
        float po  = __ldcg(&g_P[ph][sid * 3 + 1]);
        float pn  = __ldcg(&g_P[ph][sid * 3 + 2]);
        float pvv = __ldcg(&g_PV[ph][bb * 128 + nn * 64 + e]);
        float* Sm = stk + st * 4096;
        float* dst = stacks_out + (size_t)sid * 4096;
        float prev = 0.f, cur = Sm[e];
        float first = pp * pvv;
#pragma unroll 16
        for (int row = 0; row < SSIZE; row++) {
            float nxt = (row < SSIZE - 1) ? Sm[(row + 1) * 64 + e] : 0.f;
            float v;
            if (row == 0)              v = first;
            else if (row == SSIZE - 1) v = emp;
            else v = fmaf(pp, prev, fmaf(po, nxt, pn * cur));
            dst[row * 64 + e] = v;
            prev = cur; cur = nxt;
        }
    }
}

// ---------------- softmax over S + weighted sum -> final_hidden ----------------
__global__ void __launch_bounds__(256) attn_final_k(const float* __restrict__ outputs,
                                                    const int* __restrict__ tokens,
                                                    const float* __restrict__ ba2,
                                                    float* __restrict__ fh) {
    int b = blockIdx.x;
    int tid = threadIdx.x;
    int lane = tid & 31, wid = tid >> 5;
    __shared__ float a_sm[S_];
    __shared__ float rmax[8];
    __shared__ float rsum[8];

    float v = g_spart[0][tid * B_ + b] + g_spart[1][tid * B_ + b] + ba2[0];
    if (tokens[tid * B_ + b] == 0) v = -1e30f;

    float m = v;
#pragma unroll
    for (int off = 16; off > 0; off >>= 1) m = fmaxf(m, __shfl_xor_sync(0xffffffffu, m, off));
    if (lane == 0) rmax[wid] = m;
    __syncthreads();
    float mx = rmax[0];
#pragma unroll
    for (int i = 1; i < 8; i++) mx = fmaxf(mx, rmax[i]);
    float e = expf(v - mx);
    float sum = e;
#pragma unroll
    for (int off = 16; off > 0; off >>= 1) sum += __shfl_xor_sync(0xffffffffu, sum, off);
    if (lane == 0) rsum[wid] = sum;
    __syncthreads();
    float tot = rsum[0];
#pragma unroll
    for (int i = 1; i < 8; i++) tot += rsum[i];
    a_sm[tid] = e / tot;
    __syncthreads();

    float acc = 0.f;
    for (int s2 = 0; s2 < S_; s2++)
        acc += a_sm[s2] * outputs[((size_t)s2 * B_ + b) * H_ + tid];
    fh[b * H_ + tid] = acc;
}

// ---------------- launch ----------------
extern "C" void kernel_launch(void* const* d_in, const int* in_sizes, int n_in,
                              void* d_out, int out_size) {
    const int*   tokens     = (const int*)d_in[0];
    const float* emb        = (const float*)d_in[1];
    const float* W_ih       = (const float*)d_in[2];
    const float* W_hh       = (const float*)d_in[3];
    const float* b_ih       = (const float*)d_in[4];
    const float* b_hh       = (const float*)d_in[5];
    const float* W_act      = (const float*)d_in[6];
    const float* b_act      = (const float*)d_in[7];
    const float* W_stk      = (const float*)d_in[8];
    const float* b_stk      = (const float*)d_in[9];
    const float* empty_elem = (const float*)d_in[10];
    // d_in[11]=W_up, d_in[12]=W_down : shift matrices, hardcoded
    const float* Wa1        = (const float*)d_in[13];
    const float* ba1        = (const float*)d_in[14];
    const float* Wa2        = (const float*)d_in[15];
    const float* ba2        = (const float*)d_in[16];

    float* out     = (float*)d_out;
    float* outputs = out;
    float* fh      = out + (size_t)S_ * B_ * H_;
    float* stacks  = fh + (size_t)B_ * H_;

    float *pWihT, *pWa1T, *pEMB;
    cudaGetSymbolAddress((void**)&pWihT, g_WihT);
    cudaGetSymbolAddress((void**)&pWa1T, g_Wa1T);
    cudaGetSymbolAddress((void**)&pEMB,  g_EMB_GI);

    static int smem_set = 0;
    if (!smem_set) {
        cudaFuncSetAttribute(persist_k, cudaFuncAttributeMaxDynamicSharedMemorySize, SMEM_DYN);
        smem_set = 1;
    }

    // idx 0-1: prep (merged so persist lands at my idx 3 = ncu capture slot 5)
    prep1<<<(H3 * H_ + 255) / 256, 256>>>(W_ih, W_hh);
    prep2<<<(B_ * H_ + 255) / 256, 256>>>(W_stk, Wa1);

    // idx 2: EMB_GI = emb @ W_ih^T + b_ih  (32000 x 768)
    {
        dim3 grid(H3 / 128, VOCAB_ / 128);
        sgemm128_k<false><<<grid, 256>>>(emb, pWihT, b_ih, pEMB, nullptr, VOCAB_, H3, H_);
    }

    // idx 3: the whole recurrence in ONE persistent kernel
    persist_k<<<NBLK, 256, SMEM_DYN>>>(tokens, b_ih, b_hh, W_act, b_act, b_stk,
                                       empty_elem, outputs, stacks);

    // idx 4: attention partials
    {
        dim3 grid(H_ / 128, (S_ * B_) / 128);
        sgemm128_k<true><<<grid, 256>>>(outputs, pWa1T, ba1, nullptr, Wa2, S_ * B_, H_, H_);
    }
    // idx 5: softmax + weighted sum
    attn_final_k<<<B_, 256>>>(outputs, tokens, ba2, fh);
}

// round 12
// speedup vs baseline: 1.3955x; 1.1451x over previous
#include <cuda_runtime.h>
#include <math.h>

#define S_ 256
#define B_ 512
#define H_ 256
#define H3 768
#define VOCAB_ 32000
#define SSIZE 64
#define ELEM 64
#define NBLK 128
#define APAD 260   // A row stride (floats), 1040B, 16B multiple

// ---------------- device scratch ----------------
__device__ float g_EMB_GI[VOCAB_ * H3];
__device__ float g_WihT[H_ * H3];
__device__ float g_WhhT[H_ * H3];
__device__ float g_WstkT[H_ * 128];
__device__ float g_Wa1T[H_ * H_];
__device__ float g_h[2][B_ * H_];
__device__ float g_spart[2][S_ * B_];
__device__ unsigned int g_bar;

__device__ __forceinline__ float sigmoidf_(float x) { return 1.f / (1.f + expf(-x)); }

// ---------------- cp.async helpers ----------------
__device__ __forceinline__ void cp16(float* dst_smem, const float* src) {
    unsigned d = (unsigned)__cvta_generic_to_shared(dst_smem);
    asm volatile("cp.async.cg.shared.global [%0], [%1], 16;" :: "r"(d), "l"(src));
}
__device__ __forceinline__ void cp_commit() { asm volatile("cp.async.commit_group;"); }
template <int N>
__device__ __forceinline__ void cp_wait() { asm volatile("cp.async.wait_group %0;" :: "n"(N)); }

// ---------------- prep (persist = my launch idx 3 = ncu slot 5) ----------------
__global__ void prep1(const float* __restrict__ W_ih, const float* __restrict__ W_hh) {
    int idx = blockIdx.x * 256 + threadIdx.x;
    if (idx < H3 * H_) {
        int r = idx % H3, c = idx / H3;
        g_WihT[idx] = W_ih[r * H_ + c];
        g_WhhT[idx] = W_hh[r * H_ + c];
    }
}
__global__ void prep2(const float* __restrict__ W_stk, const float* __restrict__ Wa1) {
    int idx = blockIdx.x * 256 + threadIdx.x;
    if (idx < 128 * H_) { int r = idx % 128, c = idx / 128; g_WstkT[idx] = W_stk[r * H_ + c]; }
    if (idx < H_ * H_) { int r = idx % H_, c = idx / H_; g_Wa1T[idx] = Wa1[r * H_ + c]; }
    if (idx < B_ * H_) g_h[0][idx] = 0.f;
    if (idx == 0) g_bar = 0u;
}

// ---------------- 128x128x16 SGEMM (plain FFMA) ----------------
template <bool SCORE>
__global__ void __launch_bounds__(256) sgemm128_k(
    const float* __restrict__ A, const float* __restrict__ Bm,
    const float* __restrict__ bias, float* __restrict__ C,
    const float* __restrict__ Wa2,
    int M, int N, int K)
{
    __shared__ __align__(16) float As[16][128];
    __shared__ __align__(16) float Bs[16][128];
    int tid = threadIdx.x;
    int m0 = blockIdx.y * 128, n0 = blockIdx.x * 128;
    int tx = tid & 15, ty = tid >> 4;
    float acc[2][2][4][4] = {};

    for (int k0 = 0; k0 < K; k0 += 16) {
#pragma unroll
        for (int i = 0; i < 2; i++) {
            int f = tid * 2 + i;
            int arow = f >> 2, aq = (f & 3) * 4;
            float4 v = *(const float4*)&A[(size_t)(m0 + arow) * K + k0 + aq];
            As[aq + 0][arow] = v.x; As[aq + 1][arow] = v.y;
            As[aq + 2][arow] = v.z; As[aq + 3][arow] = v.w;
            int brow = f >> 5, bc = (f & 31) * 4;
            *(float4*)&Bs[brow][bc] = *(const float4*)&Bm[(size_t)(k0 + brow) * N + n0 + bc];
        }
        __syncthreads();
#pragma unroll
        for (int kk = 0; kk < 16; kk++) {
            float a[2][4], b[2][4];
            *(float4*)a[0] = *(float4*)&As[kk][ty * 4];
            *(float4*)a[1] = *(float4*)&As[kk][ty * 4 + 64];
            *(float4*)b[0] = *(float4*)&Bs[kk][tx * 4];
            *(float4*)b[1] = *(float4*)&Bs[kk][tx * 4 + 64];
#pragma unroll
            for (int ic = 0; ic < 2; ic++)
#pragma unroll
                for (int jc = 0; jc < 2; jc++)
#pragma unroll
                    for (int i = 0; i < 4; i++)
#pragma unroll
                        for (int j = 0; j < 4; j++)
                            acc[ic][jc][i][j] = fmaf(a[ic][i], b[jc][j], acc[ic][jc][i][j]);
        }
        __syncthreads();
    }

    if (!SCORE) {
#pragma unroll
        for (int ic = 0; ic < 2; ic++)
#pragma unroll
            for (int i = 0; i < 4; i++) {
                int m = m0 + ic * 64 + ty * 4 + i;
#pragma unroll
                for (int jc = 0; jc < 2; jc++) {
                    int n = n0 + jc * 64 + tx * 4;
                    float4 o;
                    o.x = acc[ic][jc][i][0] + bias[n + 0];
                    o.y = acc[ic][jc][i][1] + bias[n + 1];
                    o.z = acc[ic][jc][i][2] + bias[n + 2];
                    o.w = acc[ic][jc][i][3] + bias[n + 3];
                    *(float4*)&C[(size_t)m * N + n] = o;
                }
            }
    } else {
        float4 bb[2], ww[2];
#pragma unroll
        for (int jc = 0; jc < 2; jc++) {
            int n = n0 + jc * 64 + tx * 4;
            bb[jc] = *(const float4*)&bias[n];
            ww[jc] = *(const float4*)&Wa2[n];
        }
#pragma unroll
        for (int ic = 0; ic < 2; ic++)
#pragma unroll
            for (int i = 0; i < 4; i++) {
                float p = 0.f;
#pragma unroll
                for (int jc = 0; jc < 2; jc++) {
                    p += tanhf(acc[ic][jc][i][0] + bb[jc].x) * ww[jc].x;
                    p += tanhf(acc[ic][jc][i][1] + bb[jc].y) * ww[jc].y;
                    p += tanhf(acc[ic][jc][i][2] + bb[jc].z) * ww[jc].z;
                    p += tanhf(acc[ic][jc][i][3] + bb[jc].w) * ww[jc].w;
                }
#pragma unroll
                for (int off = 8; off > 0; off >>= 1)
                    p += __shfl_xor_sync(0xffffffffu, p, off);
                if (tx == 0) {
                    int m = m0 + ic * 64 + ty * 4 + i;
                    g_spart[blockIdx.x][m] = p;
                }
            }
    }
}

// ---------------- persistent recurrence: 128 uniform blocks, 1/SM ----------------
// Per block per step: GRU tile (16b x 64j x 3 gates) + AUX tile (4b x 128) + ACT
// + 8 SMEM stacks. P/PV are block-local smem ping-pong. Grid barrier per step.
// SMEM float offsets:
#define OFF_STK  0                     // 8 * 4096 = 32768
#define OFF_A    32768                 // [16][APAD] = 4160
#define OFF_AA   36928                 // [4][APAD]  = 1040
#define OFF_B    37968                 // 2 * 3136   = 6272
#define OFF_BA   44240                 // 2 * 2112   = 4224
#define OFF_PV   48464                 // 2 * 512    = 1024
#define OFF_P    49488                 // 2 * 24     = 48
#define OFF_LG   49536                 // 24
#define SMEM_DYN ((49560 + 8) * 4)

__global__ void __launch_bounds__(256, 1) persist_k(
    const int* __restrict__ tokens,
    const float* __restrict__ b_ih,
    const float* __restrict__ b_hh,
    const float* __restrict__ W_act,
    const float* __restrict__ b_act,
    const float* __restrict__ b_stk,
    const float* __restrict__ empty_elem,
    float* __restrict__ outputs,
    float* __restrict__ stacks_out)
{
    extern __shared__ __align__(16) float smem[];
    float* stk   = smem + OFF_STK;
    float* A     = smem + OFF_A;
    float* Aa    = smem + OFF_AA;
    float* B0    = smem + OFF_B;
    float* BsA   = smem + OFF_BA;
    float* pvbuf = smem + OFF_PV;
    float* pbuf  = smem + OFF_P;
    float* lg    = smem + OFF_LG;

    int tid = threadIdx.x, blk = blockIdx.x;
    float emp = empty_elem[tid & 63];

    for (int i = tid; i < 8 * 4096; i += 256) stk[i] = empty_elem[i & 63];

    // GRU mapping: 32 mtiles(16b) x 4 jtiles(64j)
    int b0 = (blk >> 2) * 16, j0 = (blk & 3) * 64;
    int tx = tid & 31, tyw = tid >> 5;          // 2 j-cols, 2 rows
    int r0 = b0 + tyw * 2;
    // AUX mapping
    int ab0 = blk * 4;
    int aty = tid >> 6, atx = tid & 63;
    int wwid = tid >> 5, lane = tid & 31;

    for (int s = 0; s < S_; s++) {
        const float* hin = g_h[s & 1];
        float* hout = g_h[(s + 1) & 1];

        // ---- stage A (16 GRU rows) + Aa (4 AUX rows) ----
        {
            int m = tid >> 4, kq = (tid & 15) * 16;
            const float* src = hin + (b0 + m) * H_ + kq;
            float4 v0 = __ldcg((const float4*)(src + 0));
            float4 v1 = __ldcg((const float4*)(src + 4));
            float4 v2 = __ldcg((const float4*)(src + 8));
            float4 v3 = __ldcg((const float4*)(src + 12));
            float* d = A + m * APAD + kq;
            *(float4*)(d + 0) = v0; *(float4*)(d + 4)  = v1;
            *(float4*)(d + 8) = v2; *(float4*)(d + 12) = v3;
        }
        {
            int m = tid >> 6, kq = (tid & 63) * 4;
            float4 v = __ldcg((const float4*)(hin + (ab0 + m) * H_ + kq));
            *(float4*)(Aa + m * APAD + kq) = v;
        }

        // ---- GRU epilogue operand prefetch (hidden under GEMM) ----
        int jj = j0 + tx * 2;
        int tok0 = __ldg(&tokens[s * B_ + r0]);
        int tok1 = __ldg(&tokens[s * B_ + r0 + 1]);
        const float* gi0 = (tok0 == 0) ? b_ih : (g_EMB_GI + (size_t)tok0 * H3);
        const float* gi1 = (tok1 == 0) ? b_ih : (g_EMB_GI + (size_t)tok1 * H3);
        float2 g0r = *(const float2*)(gi0 + jj);
        float2 g0z = *(const float2*)(gi0 + H_ + jj);
        float2 g0n = *(const float2*)(gi0 + 2 * H_ + jj);
        float2 g1r = *(const float2*)(gi1 + jj);
        float2 g1z = *(const float2*)(gi1 + H_ + jj);
        float2 g1n = *(const float2*)(gi1 + 2 * H_ + jj);
        float2 hp0 = __ldcg((const float2*)(hin + r0 * H_ + jj));
        float2 hp1 = __ldcg((const float2*)(hin + (r0 + 1) * H_ + jj));

        // ---- GRU B chunk 0 prefetch ----
#pragma unroll
        for (int i = 0; i < 3; i++) {
            int idx = tid + i * 256;
            int kk = idx / 48, r = idx % 48, g = r >> 4, l = r & 15;
            cp16(B0 + kk * 196 + g * 64 + l * 4,
                 g_WhhT + (size_t)kk * H3 + g * H_ + j0 + l * 4);
        }
        cp_commit();

        float2 accr0 = {0,0}, accr1 = {0,0};
        float2 accz0 = {0,0}, accz1 = {0,0};
        float2 accn0 = {0,0}, accn1 = {0,0};
        __syncthreads();   // A, Aa visible

        for (int c = 0; c < 16; c++) {
            float* Bc = B0 + (c & 1) * 3136;
            if (c + 1 < 16) {
                float* Bn = B0 + ((c + 1) & 1) * 3136;
                int kb = (c + 1) * 16;
#pragma unroll
                for (int i = 0; i < 3; i++) {
                    int idx = tid + i * 256;
                    int kk = idx / 48, r = idx % 48, g = r >> 4, l = r & 15;
                    cp16(Bn + kk * 196 + g * 64 + l * 4,
                         g_WhhT + (size_t)(kb + kk) * H3 + g * H_ + j0 + l * 4);
                }
                cp_commit();
                cp_wait<1>();
            } else {
                cp_wait<0>();
            }
            __syncthreads();
            // hoist both A rows for this chunk to registers (uniform per warp)
            float a0[16], a1[16];
            {
                const float4* Ar0 = (const float4*)(A + (tyw * 2) * APAD + c * 16);
                const float4* Ar1 = (const float4*)(A + (tyw * 2 + 1) * APAD + c * 16);
                *(float4*)&a0[0] = Ar0[0]; *(float4*)&a0[4] = Ar0[1];
                *(float4*)&a0[8] = Ar0[2]; *(float4*)&a0[12] = Ar0[3];
                *(float4*)&a1[0] = Ar1[0]; *(float4*)&a1[4] = Ar1[1];
                *(float4*)&a1[8] = Ar1[2]; *(float4*)&a1[12] = Ar1[3];
            }
#pragma unroll
            for (int kk = 0; kk < 16; kk++) {
                float2 br = *(float2*)(Bc + kk * 196 + tx * 2);
                float2 bz = *(float2*)(Bc + kk * 196 + 64 + tx * 2);
                float2 bn = *(float2*)(Bc + kk * 196 + 128 + tx * 2);
                accr0.x = fmaf(a0[kk], br.x, accr0.x); accr0.y = fmaf(a0[kk], br.y, accr0.y);
                accr1.x = fmaf(a1[kk], br.x, accr1.x); accr1.y = fmaf(a1[kk], br.y, accr1.y);
                accz0.x = fmaf(a0[kk], bz.x, accz0.x); accz0.y = fmaf(a0[kk], bz.y, accz0.y);
                accz1.x = fmaf(a1[kk], bz.x, accz1.x); accz1.y = fmaf(a1[kk], bz.y, accz1.y);
                accn0.x = fmaf(a0[kk], bn.x, accn0.x); accn0.y = fmaf(a0[kk], bn.y, accn0.y);
                accn1.x = fmaf(a1[kk], bn.x, accn1.x); accn1.y = fmaf(a1[kk], bn.y, accn1.y);
            }
            __syncthreads();
        }

        // ---- GRU epilogue (2 rows x 2 cols) ----
        {
            float2 bhr = *(const float2*)(b_hh + jj);
            float2 bhz = *(const float2*)(b_hh + H_ + jj);
            float2 bhn = *(const float2*)(b_hh + 2 * H_ + jj);
            float2 o0, o1;
            { float rr = sigmoidf_(g0r.x + accr0.x + bhr.x);
              float zz = sigmoidf_(g0z.x + accz0.x + bhz.x);
              float nn = tanhf(g0n.x + rr * (accn0.x + bhn.x));
              o0.x = (1.f - zz) * nn + zz * hp0.x; }
            { float rr = sigmoidf_(g0r.y + accr0.y + bhr.y);
              float zz = sigmoidf_(g0z.y + accz0.y + bhz.y);
              float nn = tanhf(g0n.y + rr * (accn0.y + bhn.y));
              o0.y = (1.f - zz) * nn + zz * hp0.y; }
            { float rr = sigmoidf_(g1r.x + accr1.x + bhr.x);
              float zz = sigmoidf_(g1z.x + accz1.x + bhz.x);
              float nn = tanhf(g1n.x + rr * (accn1.x + bhn.x));
              o1.x = (1.f - zz) * nn + zz * hp1.x; }
            { float rr = sigmoidf_(g1r.y + accr1.y + bhr.y);
              float zz = sigmoidf_(g1z.y + accz1.y + bhz.y);
              float nn = tanhf(g1n.y + rr * (accn1.y + bhn.y));
              o1.y = (1.f - zz) * nn + zz * hp1.y; }
            *(float2*)(hout + r0 * H_ + jj) = o0;
            *(float2*)(hout + (r0 + 1) * H_ + jj) = o1;
            *(float2*)(outputs + ((size_t)s * B_ + r0) * H_ + jj) = o0;
            *(float2*)(outputs + ((size_t)s * B_ + r0 + 1) * H_ + jj) = o1;
        }

        // ---- AUX GEMM: PV = tanh(h[ab0..+3] @ WstkT + b_stk) ----
#pragma unroll
        for (int i = 0; i < 2; i++) {
            int idx = tid + i * 256;
            int kk = idx >> 5, l = idx & 31;
            cp16(BsA + kk * 132 + l * 4, g_WstkT + (size_t)kk * 128 + l * 4);
        }
        cp_commit();
        float acc0 = 0.f, acc1 = 0.f;
        for (int c = 0; c < 16; c++) {
            float* Bc = BsA + (c & 1) * 2112;
            if (c + 1 < 16) {
                float* Bn = BsA + ((c + 1) & 1) * 2112;
                int kb = (c + 1) * 16;
#pragma unroll
                for (int i = 0; i < 2; i++) {
                    int idx = tid + i * 256;
                    int kk = idx >> 5, l = idx & 31;
                    cp16(Bn + kk * 132 + l * 4, g_WstkT + (size_t)(kb + kk) * 128 + l * 4);
                }
                cp_commit();
                cp_wait<1>();
            } else {
                cp_wait<0>();
            }
            __syncthreads();
            const float* Arow = Aa + aty * APAD + c * 16;
#pragma unroll
            for (int kk = 0; kk < 16; kk++) {
                float a = Arow[kk];
                float2 bv = *(float2*)(Bc + kk * 132 + atx * 2);
                acc0 = fmaf(a, bv.x, acc0);
                acc1 = fmaf(a, bv.y, acc1);
            }
            __syncthreads();
        }
        {
            int cc = atx * 2;
            float* pv = pvbuf + (s & 1) * 512 + aty * 128 + cc;
            pv[0] = tanhf(acc0 + __ldg(&b_stk[cc]));
            pv[1] = tanhf(acc1 + __ldg(&b_stk[cc + 1]));
        }
        // ---- ACT logits: 24 dots, 3 per warp, shfl-reduced ----
#pragma unroll
        for (int q = 0; q < 3; q++) {
            int d = wwid * 3 + q;
            int bl = d / 6, o = d % 6;
            const float* ar = Aa + bl * APAD;
            const float* wr = W_act + o * H_;
            float sum = 0.f;
#pragma unroll
            for (int k = lane; k < H_; k += 32)
                sum = fmaf(ar[k], __ldg(&wr[k]), sum);
#pragma unroll
            for (int off = 16; off > 0; off >>= 1)
                sum += __shfl_xor_sync(0xffffffffu, sum, off);
            if (lane == 0) lg[d] = sum + __ldg(&b_act[o]);
        }
        __syncthreads();
        if (tid < 8) {
            float l0 = lg[tid * 3 + 0], l1 = lg[tid * 3 + 1], l2 = lg[tid * 3 + 2];
            float mx = fmaxf(l0, fmaxf(l1, l2));
            float e0 = expf(l0 - mx), e1 = expf(l1 - mx), e2 = expf(l2 - mx);
            float inv = 1.f / (e0 + e1 + e2);
            float* P = pbuf + (s & 1) * 24 + tid * 3;
            P[0] = e0 * inv; P[1] = e1 * inv; P[2] = e2 * inv;
        }

        // ---- arrive ----
        __threadfence();
        __syncthreads();
        if (tid == 0) atomicAdd(&g_bar, 1u);

        // ---- stack update for step s-1 (block-local, hidden in wait window) ----
        if (s > 0) {
            int ph = (s - 1) & 1;
#pragma unroll
            for (int half = 0; half < 2; half++) {
                int col = tid + half * 256;
                int stl = col >> 6, ee = col & 63;
                float pp = pbuf[ph * 24 + stl * 3 + 0];
                float po = pbuf[ph * 24 + stl * 3 + 1];
                float pn = pbuf[ph * 24 + stl * 3 + 2];
                float pvv = pvbuf[ph * 512 + (stl >> 1) * 128 + (stl & 1) * 64 + ee];
                float* Sm = stk + stl * 4096;
                float prev = 0.f, cur = Sm[ee];
                float first = pp * pvv;
#pragma unroll 16
                for (int row = 0; row < SSIZE; row++) {
                    float nxt = (row < SSIZE - 1) ? Sm[(row + 1) * 64 + ee] : 0.f;
                    float v;
                    if (row == 0)              v = first;
                    else if (row == SSIZE - 1) v = emp;
                    else v = fmaf(pp, prev, fmaf(po, nxt, pn * cur));
                    Sm[row * 64 + ee] = v;
                    prev = cur; cur = nxt;
                }
            }
        }

        // ---- spin ----
        if (tid == 0) {
            unsigned int target = (unsigned int)NBLK * (unsigned int)(s + 1);
            while (*((volatile unsigned int*)&g_bar) < target) { }
        }
        __syncthreads();
    }

    // ---- final stack update (step S-1) -> global ----
    {
        int ph = (S_ - 1) & 1;
#pragma unroll
        for (int half = 0; half < 2; half++) {
            int col = tid + half * 256;
            int stl = col >> 6, ee = col & 63;
            float pp = pbuf[ph * 24 + stl * 3 + 0];
            float po = pbuf[ph * 24 + stl * 3 + 1];
            float pn = pbuf[ph * 24 + stl * 3 + 2];
            float pvv = pvbuf[ph * 512 + (stl >> 1) * 128 + (stl & 1) * 64 + ee];
            float* Sm = stk + stl * 4096;
            float* dst = stacks_out + (size_t)(blk * 8 + stl) * 4096;
            float prev = 0.f, cur = Sm[ee];
            float first = pp * pvv;
#pragma unroll 16
            for (int row = 0; row < SSIZE; row++) {
                float nxt = (row < SSIZE - 1) ? Sm[(row + 1) * 64 + ee] : 0.f;
                float v;
                if (row == 0)              v = first;
                else if (row == SSIZE - 1) v = emp;
                else v = fmaf(pp, prev, fmaf(po, nxt, pn * cur));
                dst[row * 64 + ee] = v;
                prev = cur; cur = nxt;
            }
        }
    }
}

// ---------------- softmax over S + weighted sum -> final_hidden ----------------
__global__ void __launch_bounds__(256) attn_final_k(const float* __restrict__ outputs,
                                                    const int* __restrict__ tokens,
                                                    const float* __restrict__ ba2,
                                                    float* __restrict__ fh) {
    int b = blockIdx.x;
    int tid = threadIdx.x;
    int lane = tid & 31, wid = tid >> 5;
    __shared__ float a_sm[S_];
    __shared__ float rmax[8];
    __shared__ float rsum[8];

    float v = g_spart[0][tid * B_ + b] + g_spart[1][tid * B_ + b] + ba2[0];
    if (tokens[tid * B_ + b] == 0) v = -1e30f;

    float m = v;
#pragma unroll
    for (int off = 16; off > 0; off >>= 1) m = fmaxf(m, __shfl_xor_sync(0xffffffffu, m, off));
    if (lane == 0) rmax[wid] = m;
    __syncthreads();
    float mx = rmax[0];
#pragma unroll
    for (int i = 1; i < 8; i++) mx = fmaxf(mx, rmax[i]);
    float e = expf(v - mx);
    float sum = e;
#pragma unroll
    for (int off = 16; off > 0; off >>= 1) sum += __shfl_xor_sync(0xffffffffu, sum, off);
    if (lane == 0) rsum[wid] = sum;
    __syncthreads();
    float tot = rsum[0];
#pragma unroll
    for (int i = 1; i < 8; i++) tot += rsum[i];
    a_sm[tid] = e / tot;
    __syncthreads();

    float acc = 0.f;
    for (int s2 = 0; s2 < S_; s2++)
        acc += a_sm[s2] * outputs[((size_t)s2 * B_ + b) * H_ + tid];
    fh[b * H_ + tid] = acc;
}

// ---------------- launch ----------------
extern "C" void kernel_launch(void* const* d_in, const int* in_sizes, int n_in,
                              void* d_out, int out_size) {
    const int*   tokens     = (const int*)d_in[0];
    const float* emb        = (const float*)d_in[1];
    const float* W_ih       = (const float*)d_in[2];
    const float* W_hh       = (const float*)d_in[3];
    const float* b_ih       = (const float*)d_in[4];
    const float* b_hh       = (const float*)d_in[5];
    const float* W_act      = (const float*)d_in[6];
    const float* b_act      = (const float*)d_in[7];
    const float* W_stk      = (const float*)d_in[8];
    const float* b_stk      = (const float*)d_in[9];
    const float* empty_elem = (const float*)d_in[10];
    // d_in[11]=W_up, d_in[12]=W_down : shift matrices, hardcoded
    const float* Wa1        = (const float*)d_in[13];
    const float* ba1        = (const float*)d_in[14];
    const float* Wa2        = (const float*)d_in[15];
    const float* ba2        = (const float*)d_in[16];

    float* out     = (float*)d_out;
    float* outputs = out;
    float* fh      = out + (size_t)S_ * B_ * H_;
    float* stacks  = fh + (size_t)B_ * H_;

    float *pWihT, *pWa1T, *pEMB;
    cudaGetSymbolAddress((void**)&pWihT, g_WihT);
    cudaGetSymbolAddress((void**)&pWa1T, g_Wa1T);
    cudaGetSymbolAddress((void**)&pEMB,  g_EMB_GI);

    static int smem_set = 0;
    if (!smem_set) {
        cudaFuncSetAttribute(persist_k, cudaFuncAttributeMaxDynamicSharedMemorySize, SMEM_DYN);
        smem_set = 1;
    }

    // idx 0-1: prep
    prep1<<<(H3 * H_ + 255) / 256, 256>>>(W_ih, W_hh);
    prep2<<<(B_ * H_ + 255) / 256, 256>>>(W_stk, Wa1);

    // idx 2: EMB_GI = emb @ W_ih^T + b_ih
    {
        dim3 grid(H3 / 128, VOCAB_ / 128);
        sgemm128_k<false><<<grid, 256>>>(emb, pWihT, b_ih, pEMB, nullptr, VOCAB_, H3, H_);
    }

    // idx 3: the whole recurrence (ncu capture slot 5)
    persist_k<<<NBLK, 256, SMEM_DYN>>>(tokens, b_ih, b_hh, W_act, b_act, b_stk,
                                       empty_elem, outputs, stacks);

    // idx 4: attention partials
    {
        dim3 grid(H_ / 128, (S_ * B_) / 128);
        sgemm128_k<true><<<grid, 256>>>(outputs, pWa1T, ba1, nullptr, Wa2, S_ * B_, H_, H_);
    }
    // idx 5: softmax + weighted sum
    attn_final_k<<<B_, 256>>>(outputs, tokens, ba2, fh);
}